// round 14
// baseline (speedup 1.0000x reference)
#include <cuda_runtime.h>
#include <cuda_bf16.h>
#include <cuda_fp16.h>
#include <math.h>

// Problem constants
#define BB 2
#define LL 4096
#define EE 256
#define HH 8
#define DD 32
#define NPAIR 16
#define QT 64     // queries per attention CTA (2 warps x 2 m-tiles)

typedef unsigned int uint32;

// ---------------- device scratch ----------------
__device__ uint32 g_qh2[16 * 65536];
__device__ uint32 g_kh2[16 * 65536];
__device__ uint32 g_vh2[16 * 65536];
__device__ float g_ao[BB*HH*LL*DD];
__device__ float g_cos[LL*NPAIR];
__device__ float g_sin[LL*NPAIR];

// ---------------- helpers ----------------
__device__ __forceinline__ uint32 h2pack(float lo, float hi) {
    uint32 r;
    asm("cvt.rn.f16x2.f32 %0, %1, %2;" : "=r"(r) : "f"(hi), "f"(lo));
    return r;
}
__device__ __forceinline__ uint32 ex2h2(uint32 x) {
    uint32 r;
    asm("ex2.approx.f16x2 %0, %1;" : "=r"(r) : "r"(x));
    return r;
}
__device__ __forceinline__ void mma_f16(float* d, const uint32* a, uint32 b0, uint32 b1) {
    asm volatile(
        "mma.sync.aligned.m16n8k16.row.col.f32.f16.f16.f32 "
        "{%0,%1,%2,%3}, {%4,%5,%6,%7}, {%8,%9}, {%0,%1,%2,%3};"
        : "+f"(d[0]), "+f"(d[1]), "+f"(d[2]), "+f"(d[3])
        : "r"(a[0]), "r"(a[1]), "r"(a[2]), "r"(a[3]), "r"(b0), "r"(b1));
}
__device__ __forceinline__ void ldsm4(uint32& r0, uint32& r1, uint32& r2, uint32& r3,
                                      uint32 addr) {
    asm volatile("ldmatrix.sync.aligned.m8n8.x4.shared.b16 {%0,%1,%2,%3}, [%4];"
                 : "=r"(r0), "=r"(r1), "=r"(r2), "=r"(r3) : "r"(addr));
}
__device__ __forceinline__ void cp16(uint32 dst, const void* src) {
    asm volatile("cp.async.cg.shared.global [%0], [%1], 16;" :: "r"(dst), "l"(src));
}
__device__ __forceinline__ void split4h(float4 v, uint2& hi, uint2& lo) {
    uint32 h01 = h2pack(v.x, v.y);
    uint32 h23 = h2pack(v.z, v.w);
    float2 f01 = __half22float2(*(__half2*)&h01);
    float2 f23 = __half22float2(*(__half2*)&h23);
    uint32 l01 = h2pack(v.x - f01.x, v.y - f01.y);
    uint32 l23 = h2pack(v.z - f23.x, v.w - f23.y);
    hi = make_uint2(h01, h23);
    lo = make_uint2(l01, l23);
}

// ---------------- rope table ----------------
__global__ void rope_table_kernel() {
    int idx = blockIdx.x * blockDim.x + threadIdx.x;
    if (idx >= LL * NPAIR) return;
    int l = idx >> 4;
    int i = idx & 15;
    float t = (i < 8) ? (float)(l & 63) : (float)(l >> 6);
    int fi = i & 7;
    float freq = powf(10000.0f, -(4.0f * (float)fi) / 32.0f);
    float ang = t * freq;
    g_cos[idx] = cosf(ang);
    g_sin[idx] = sinf(ang);
}

// ---------------- fused QKV projection: fp16 mma + ldmatrix, double-buffer --
__global__ __launch_bounds__(128)
void gemm_qkv(const float* __restrict__ qi, const float* __restrict__ ki,
              const float* __restrict__ vi,
              const float* __restrict__ Wq, const float* __restrict__ Wk,
              const float* __restrict__ Wv,
              const float* __restrict__ bq, const float* __restrict__ bk,
              const float* __restrict__ bv) {
    __shared__ __align__(16) __half As[2][64 * 40];
    __shared__ __align__(16) __half Ws[2][64 * 40];

    const int mode = blockIdx.z;
    const float* A    = (mode == 0) ? qi : (mode == 1) ? ki : vi;
    const float* W    = (mode == 0) ? Wq : (mode == 1) ? Wk : Wv;
    const float* bias = (mode == 0) ? bq : (mode == 1) ? bk : bv;

    const int tid = threadIdx.x;
    const int w = tid >> 5, lane = tid & 31;
    const int quad = lane >> 2, cm = lane & 3;
    const int wm = w >> 1, wn = w & 1;
    const int m0 = blockIdx.y * 64;
    const int n0 = blockIdx.x * 64;

    float C[2][4][4];
#pragma unroll
    for (int mt = 0; mt < 2; mt++)
#pragma unroll
        for (int nt = 0; nt < 4; nt++)
#pragma unroll
            for (int j = 0; j < 4; j++) C[mt][nt][j] = 0.0f;

    const uint32 abase = (uint32)__cvta_generic_to_shared(&As[0][0]);
    const uint32 wbase = (uint32)__cvta_generic_to_shared(&Ws[0][0]);
    const int matid = lane >> 3, rowin = lane & 7;
    uint32 aAddr[2][2], bAddr[2][2];
#pragma unroll
    for (int mt = 0; mt < 2; mt++)
#pragma unroll
        for (int ks = 0; ks < 2; ks++) {
            int row = wm * 32 + mt * 16 + (matid & 1) * 8 + rowin;
            int kc = ks * 16 + (matid >> 1) * 8;
            aAddr[mt][ks] = abase + (row * 40 + kc) * 2;
        }
#pragma unroll
    for (int pr = 0; pr < 2; pr++)
#pragma unroll
        for (int ks = 0; ks < 2; ks++) {
            int n = wn * 32 + (pr * 2 + (matid >> 1)) * 8 + rowin;
            int kc = ks * 16 + (matid & 1) * 8;
            bAddr[pr][ks] = wbase + (n * 40 + kc) * 2;
        }

    float4 pa[4], pw[4];
    const int grow = tid >> 3, gc4 = tid & 7;

#define QKV_LOAD(ch)                                                          \
    {                                                                         \
        _Pragma("unroll")                                                     \
        for (int i = 0; i < 4; i++) {                                         \
            int row = grow + 16 * i;                                          \
            pa[i] = *(const float4*)(A + (size_t)(m0 + row) * 256 + (ch) * 32 + gc4 * 4); \
            pw[i] = *(const float4*)(W + (size_t)(n0 + row) * 256 + (ch) * 32 + gc4 * 4); \
        }                                                                     \
    }
#define QKV_STS(buf)                                                          \
    {                                                                         \
        _Pragma("unroll")                                                     \
        for (int i = 0; i < 4; i++) {                                         \
            int row = grow + 16 * i;                                          \
            *(uint2*)(&As[buf][row * 40 + gc4 * 4]) =                         \
                make_uint2(h2pack(pa[i].x, pa[i].y), h2pack(pa[i].z, pa[i].w)); \
            *(uint2*)(&Ws[buf][row * 40 + gc4 * 4]) =                         \
                make_uint2(h2pack(pw[i].x, pw[i].y), h2pack(pw[i].z, pw[i].w)); \
        }                                                                     \
    }

    QKV_LOAD(0);
    QKV_STS(0);
    QKV_LOAD(1);
    __syncthreads();

#pragma unroll
    for (int ch = 0; ch < 8; ch++) {
        const int buf = ch & 1;
        const uint32 boff = buf * (64 * 40 * 2);

        uint32 aF[2][2][4];
#pragma unroll
        for (int mt = 0; mt < 2; mt++)
#pragma unroll
            for (int ks = 0; ks < 2; ks++)
                ldsm4(aF[mt][ks][0], aF[mt][ks][1], aF[mt][ks][2], aF[mt][ks][3],
                      aAddr[mt][ks] + boff);
        uint32 bF[4][2][2];
#pragma unroll
        for (int pr = 0; pr < 2; pr++)
#pragma unroll
            for (int ks = 0; ks < 2; ks++) {
                uint32 r0, r1, r2, r3;
                ldsm4(r0, r1, r2, r3, bAddr[pr][ks] + boff);
                bF[2 * pr][ks][0] = r0; bF[2 * pr][ks][1] = r1;
                bF[2 * pr + 1][ks][0] = r2; bF[2 * pr + 1][ks][1] = r3;
            }

        if (ch < 7) QKV_STS(buf ^ 1);
        if (ch < 6) QKV_LOAD(ch + 2);
        __syncthreads();

#pragma unroll
        for (int ks = 0; ks < 2; ks++)
#pragma unroll
            for (int mt = 0; mt < 2; mt++)
#pragma unroll
                for (int nt = 0; nt < 4; nt++)
                    mma_f16(C[mt][nt], aF[mt][ks], bF[nt][ks][0], bF[nt][ks][1]);
    }

    // ---- epilogue: rope + frag-layout scatter ----
    const float QS = 0.17677669529663687f * 1.4426950408889634f;
#pragma unroll
    for (int mt = 0; mt < 2; mt++) {
        int row0 = m0 + wm * 32 + mt * 16 + quad;
#pragma unroll
        for (int nt = 0; nt < 4; nt++) {
            int col = n0 + wn * 32 + nt * 8 + 2 * cm;
            float b0 = bias[col], b1 = bias[col + 1];
#pragma unroll
            for (int half_ = 0; half_ < 2; half_++) {
                int row = row0 + half_ * 8;
                float real = C[mt][nt][half_ * 2 + 0] + b0;
                float imag = C[mt][nt][half_ * 2 + 1] + b1;
                int l = row & 4095, b = row >> 12;
                int h = col >> 5, d = col & 31;
                if (mode == 2) {
                    __half* dsth = (__half*)g_vh2 + (size_t)(b * 8 + h) * 131072;
                    int tile = l >> 6, rl = l & 63;
                    int kst2 = rl >> 4, rk = rl & 15;
                    int plane = rk >> 3, t4 = (rk & 7) >> 1, lh = rk & 1;
                    int nd = d >> 3, g0 = d & 7;
                    int i0 = ((((tile * 16 + kst2 * 4 + nd) * 32 + (g0 * 4 + t4)) * 2 + plane)) * 2 + lh;
                    int i1 = ((((tile * 16 + kst2 * 4 + nd) * 32 + ((g0 + 1) * 4 + t4)) * 2 + plane)) * 2 + lh;
                    dsth[i0] = __float2half(real);
                    dsth[i1] = __float2half(imag);
                } else {
                    int p = d >> 1;
                    float cs = g_cos[l * NPAIR + p];
                    float sn = g_sin[l * NPAIR + p];
                    float out_r = real * cs - imag * sn;
                    float out_i = real * sn + imag * cs;
                    if (mode == 0) { out_r *= QS; out_i *= QS; }
                    uint32* dst = ((mode == 0) ? g_qh2 : g_kh2) + (size_t)(b * 8 + h) * 65536;
                    int ks = d >> 4, dc = d & 15;
                    uint32 packed = h2pack(out_r, out_i);
                    if (mode == 0) {
                        int rg = l >> 4, r = l & 15;
                        int areg = (r >> 3) + ((dc >> 3) << 1);
                        int ln = (r & 7) * 4 + ((dc & 7) >> 1);
                        dst[((rg * 2 + ks) * 4 + areg) * 32 + ln] = packed;
                    } else {
                        int tile = l >> 6, ng = (l & 63) >> 3;
                        int plane = dc >> 3;
                        int ln = (l & 7) * 4 + ((dc & 7) >> 1);
                        dst[(((tile * 8 + ng) * 2 + ks) * 32 + ln) * 2 + plane] = packed;
                    }
                }
            }
        }
    }
}

// ---------------- output projection: fp16 x2 split, double-buffer ----------
__global__ __launch_bounds__(128, 4)
void gemm_out(const float* __restrict__ W, const float* __restrict__ bias,
              float* __restrict__ out) {
    __shared__ __align__(16) __half Ah[2][64 * 40];
    __shared__ __align__(16) __half Al[2][64 * 40];
    __shared__ __align__(16) __half Wh[2][64 * 40];
    __shared__ __align__(16) __half Wl[2][64 * 40];

    const int tid = threadIdx.x;
    const int w = tid >> 5, lane = tid & 31;
    const int quad = lane >> 2, cm = lane & 3;
    const int wm = w >> 1, wn = w & 1;
    const int m0 = blockIdx.y * 64;
    const int n0 = blockIdx.x * 64;

    float C[2][4][4];
#pragma unroll
    for (int mt = 0; mt < 2; mt++)
#pragma unroll
        for (int nt = 0; nt < 4; nt++)
#pragma unroll
            for (int j = 0; j < 4; j++) C[mt][nt][j] = 0.0f;

    const uint32 ahb = (uint32)__cvta_generic_to_shared(&Ah[0][0]);
    const uint32 alb = (uint32)__cvta_generic_to_shared(&Al[0][0]);
    const uint32 whb = (uint32)__cvta_generic_to_shared(&Wh[0][0]);
    const uint32 wlb = (uint32)__cvta_generic_to_shared(&Wl[0][0]);
    const int matid = lane >> 3, rowin = lane & 7;
    uint32 aOff[2][2], bOff[2][2];
#pragma unroll
    for (int mt = 0; mt < 2; mt++)
#pragma unroll
        for (int ks = 0; ks < 2; ks++) {
            int row = wm * 32 + mt * 16 + (matid & 1) * 8 + rowin;
            int kc = ks * 16 + (matid >> 1) * 8;
            aOff[mt][ks] = (row * 40 + kc) * 2;
        }
#pragma unroll
    for (int pr = 0; pr < 2; pr++)
#pragma unroll
        for (int ks = 0; ks < 2; ks++) {
            int n = wn * 32 + (pr * 2 + (matid >> 1)) * 8 + rowin;
            int kc = ks * 16 + (matid & 1) * 8;
            bOff[pr][ks] = (n * 40 + kc) * 2;
        }

    float4 pa[4], pw[4];
    const int grow = tid >> 3, gc4 = tid & 7;

#define OUT_LOAD(ch)                                                          \
    {                                                                         \
        _Pragma("unroll")                                                     \
        for (int i = 0; i < 4; i++) {                                         \
            int row = grow + 16 * i;                                          \
            int m = m0 + row;                                                 \
            int b = m >> 12, l = m & 4095;                                    \
            pa[i] = *(const float4*)(g_ao + (((size_t)(b * 8 + (ch)) * 4096) + l) * 32 + gc4 * 4); \
            pw[i] = *(const float4*)(W + (size_t)(n0 + row) * 256 + (ch) * 32 + gc4 * 4); \
        }                                                                     \
    }
#define OUT_STS(buf)                                                          \
    {                                                                         \
        _Pragma("unroll")                                                     \
        for (int i = 0; i < 4; i++) {                                         \
            int row = grow + 16 * i;                                          \
            uint2 hi, lo;                                                     \
            split4h(pa[i], hi, lo);                                           \
            *(uint2*)(&Ah[buf][row * 40 + gc4 * 4]) = hi;                     \
            *(uint2*)(&Al[buf][row * 40 + gc4 * 4]) = lo;                     \
            split4h(pw[i], hi, lo);                                           \
            *(uint2*)(&Wh[buf][row * 40 + gc4 * 4]) = hi;                     \
            *(uint2*)(&Wl[buf][row * 40 + gc4 * 4]) = lo;                     \
        }                                                                     \
    }

    OUT_LOAD(0);
    OUT_STS(0);
    OUT_LOAD(1);
    __syncthreads();

#pragma unroll
    for (int ch = 0; ch < 8; ch++) {
        const int buf = ch & 1;
        const uint32 boff = buf * (64 * 40 * 2);

        uint32 aH[2][2][4], aL[2][2][4];
#pragma unroll
        for (int mt = 0; mt < 2; mt++)
#pragma unroll
            for (int ks = 0; ks < 2; ks++) {
                ldsm4(aH[mt][ks][0], aH[mt][ks][1], aH[mt][ks][2], aH[mt][ks][3],
                      ahb + aOff[mt][ks] + boff);
                ldsm4(aL[mt][ks][0], aL[mt][ks][1], aL[mt][ks][2], aL[mt][ks][3],
                      alb + aOff[mt][ks] + boff);
            }
        uint32 bH[4][2][2], bL[4][2][2];
#pragma unroll
        for (int pr = 0; pr < 2; pr++)
#pragma unroll
            for (int ks = 0; ks < 2; ks++) {
                uint32 r0, r1, r2, r3;
                ldsm4(r0, r1, r2, r3, whb + bOff[pr][ks] + boff);
                bH[2 * pr][ks][0] = r0; bH[2 * pr][ks][1] = r1;
                bH[2 * pr + 1][ks][0] = r2; bH[2 * pr + 1][ks][1] = r3;
                ldsm4(r0, r1, r2, r3, wlb + bOff[pr][ks] + boff);
                bL[2 * pr][ks][0] = r0; bL[2 * pr][ks][1] = r1;
                bL[2 * pr + 1][ks][0] = r2; bL[2 * pr + 1][ks][1] = r3;
            }

        if (ch < 7) OUT_STS(buf ^ 1);
        if (ch < 6) OUT_LOAD(ch + 2);
        __syncthreads();

#pragma unroll
        for (int ks = 0; ks < 2; ks++)
#pragma unroll
            for (int mt = 0; mt < 2; mt++)
#pragma unroll
                for (int nt = 0; nt < 4; nt++) {
                    mma_f16(C[mt][nt], aH[mt][ks], bH[nt][ks][0], bH[nt][ks][1]);
                    mma_f16(C[mt][nt], aL[mt][ks], bH[nt][ks][0], bH[nt][ks][1]);
                    mma_f16(C[mt][nt], aH[mt][ks], bL[nt][ks][0], bL[nt][ks][1]);
                }
    }

#pragma unroll
    for (int mt = 0; mt < 2; mt++) {
        int row0 = m0 + wm * 32 + mt * 16 + quad;
#pragma unroll
        for (int nt = 0; nt < 4; nt++) {
            int col = n0 + wn * 32 + nt * 8 + 2 * cm;
            float b0 = bias[col], b1 = bias[col + 1];
#pragma unroll
            for (int half_ = 0; half_ < 2; half_++) {
                int row = row0 + half_ * 8;
                float real = C[mt][nt][half_ * 2 + 0] + b0;
                float imag = C[mt][nt][half_ * 2 + 1] + b1;
                *(float2*)(out + (size_t)row * 256 + col) = make_float2(real, imag);
            }
        }
    }
}

// ---------------- flash attention: 64-thread CTAs, 2 m-tiles/warp ----------
__global__ __launch_bounds__(64, 8)
void attn_mma() {
    __shared__ __align__(16) uint32 sK[2][1024];
    __shared__ __align__(16) uint32 sV[2][1024];

    const int tid = threadIdx.x;
    const int w = tid >> 5;          // 0..1
    const int lane = tid & 31;
    const int quad = lane >> 2;
    const int cm = lane & 3;
    const int bh = blockIdx.y;
    const int q0 = blockIdx.x * QT;
    const uint32 ONES2 = 0x3C003C00u;

    const uint32* Q2 = g_qh2 + (size_t)bh * 65536;
    const uint32* K2 = g_kh2 + (size_t)bh * 65536;
    const uint32* V2 = g_vh2 + (size_t)bh * 65536;

    // ---- Q fp16 A-fragments (2 m-tiles per warp) ----
    uint32 qf[2][2][4];
#pragma unroll
    for (int mt = 0; mt < 2; mt++) {
        int rg = ((q0 + w * 32 + mt * 16) >> 4);
#pragma unroll
        for (int ks = 0; ks < 2; ks++)
#pragma unroll
            for (int ar = 0; ar < 4; ar++)
                qf[mt][ks][ar] = Q2[((rg * 2 + ks) * 4 + ar) * 32 + lane];
    }

    float O[2][4][4];
#pragma unroll
    for (int mt = 0; mt < 2; mt++)
#pragma unroll
        for (int nd = 0; nd < 4; nd++)
#pragma unroll
            for (int j = 0; j < 4; j++) O[mt][nd][j] = 0.0f;

    float Lac[2][4];
#pragma unroll
    for (int mt = 0; mt < 2; mt++)
#pragma unroll
        for (int j = 0; j < 4; j++) Lac[mt][j] = 0.0f;

    const uint32 sKb = (uint32)__cvta_generic_to_shared(&sK[0][0]);
    const uint32 sVb = (uint32)__cvta_generic_to_shared(&sV[0][0]);

    // issue tile 0: K 4KB + V 4KB over 64 threads -> 4 cp16 each per buffer
    {
        const float4* Kg = (const float4*)K2;
        const float4* Vg = (const float4*)V2;
#pragma unroll
        for (int i = 0; i < 4; i++) {
            cp16(sKb + (tid + 64 * i) * 16, Kg + tid + 64 * i);
            cp16(sVb + (tid + 64 * i) * 16, Vg + tid + 64 * i);
        }
        asm volatile("cp.async.commit_group;");
    }

    for (int t = 0; t < LL / 64; t++) {
        const int buf = t & 1;
        if (t + 1 < LL / 64) {
            const float4* Kg = (const float4*)(K2 + (size_t)(t + 1) * 1024);
            const float4* Vg = (const float4*)(V2 + (size_t)(t + 1) * 1024);
            uint32 dK = sKb + (buf ^ 1) * 4096;
            uint32 dV = sVb + (buf ^ 1) * 4096;
#pragma unroll
            for (int i = 0; i < 4; i++) {
                cp16(dK + (tid + 64 * i) * 16, Kg + tid + 64 * i);
                cp16(dV + (tid + 64 * i) * 16, Vg + tid + 64 * i);
            }
            asm volatile("cp.async.commit_group;");
            asm volatile("cp.async.wait_group 1;");
        } else {
            asm volatile("cp.async.wait_group 0;");
        }
        __syncthreads();

        const uint2* Kt = (const uint2*)sK[buf];
        const uint2* Vt = (const uint2*)sV[buf];

        uint32 aP[2][4];

#pragma unroll
        for (int n = 0; n < 8; n++) {
            uint2 kb0 = Kt[(n * 2 + 0) * 32 + lane];
            uint2 kb1 = Kt[(n * 2 + 1) * 32 + lane];
            float S0[4] = {0.f, 0.f, 0.f, 0.f};
            float S1[4] = {0.f, 0.f, 0.f, 0.f};
            mma_f16(S0, qf[0][0], kb0.x, kb0.y);
            mma_f16(S0, qf[0][1], kb1.x, kb1.y);
            mma_f16(S1, qf[1][0], kb0.x, kb0.y);
            mma_f16(S1, qf[1][1], kb1.x, kb1.y);

            const int off = (n & 1) * 2;
            aP[0][off + 0] = ex2h2(h2pack(S0[0], S0[1]));
            aP[0][off + 1] = ex2h2(h2pack(S0[2], S0[3]));
            aP[1][off + 0] = ex2h2(h2pack(S1[0], S1[1]));
            aP[1][off + 1] = ex2h2(h2pack(S1[2], S1[3]));

            if (n & 1) {
                const int kst2 = n >> 1;
                mma_f16(Lac[0], aP[0], ONES2, ONES2);
                mma_f16(Lac[1], aP[1], ONES2, ONES2);
#pragma unroll
                for (int nd = 0; nd < 4; nd++) {
                    uint2 vv = Vt[(kst2 * 4 + nd) * 32 + lane];
                    mma_f16(O[0][nd], aP[0], vv.x, vv.y);
                    mma_f16(O[1][nd], aP[1], vv.x, vv.y);
                }
            }
        }
        __syncthreads();
    }

    // ---- epilogue ----
    float* aob = g_ao + (size_t)bh * LL * DD;
#pragma unroll
    for (int mt = 0; mt < 2; mt++) {
        float i0 = 1.0f / Lac[mt][0];
        float i1 = 1.0f / Lac[mt][2];
        int qrow = q0 + w * 32 + mt * 16 + quad;
#pragma unroll
        for (int nd = 0; nd < 4; nd++) {
            float2 v0 = make_float2(O[mt][nd][0] * i0, O[mt][nd][1] * i0);
            float2 v1 = make_float2(O[mt][nd][2] * i1, O[mt][nd][3] * i1);
            *(float2*)(aob + (size_t)qrow * DD + 8 * nd + 2 * cm) = v0;
            *(float2*)(aob + (size_t)(qrow + 8) * DD + 8 * nd + 2 * cm) = v1;
        }
    }
}

// ---------------- launcher ----------------
extern "C" void kernel_launch(void* const* d_in, const int* in_sizes, int n_in,
                              void* d_out, int out_size) {
    const float* q  = (const float*)d_in[0];
    const float* k  = (const float*)d_in[1];
    const float* v  = (const float*)d_in[2];
    const float* Wq = (const float*)d_in[3];
    const float* bq = (const float*)d_in[4];
    const float* Wk = (const float*)d_in[5];
    const float* bk = (const float*)d_in[6];
    const float* Wv = (const float*)d_in[7];
    const float* bv = (const float*)d_in[8];
    const float* Wo = (const float*)d_in[9];
    const float* bo = (const float*)d_in[10];
    float* out = (float*)d_out;

    rope_table_kernel<<<(LL * NPAIR + 255) / 256, 256>>>();

    dim3 g3(EE / 64, (BB * LL) / 64, 3);  // (4, 128, 3) — fused Q/K/V
    gemm_qkv<<<g3, 128>>>(q, k, v, Wq, Wk, Wv, bq, bk, bv);

    attn_mma<<<dim3(LL / QT, BB * HH), 64>>>();   // (64, 16) x 64 threads

    dim3 gg(EE / 64, (BB * LL) / 64);  // (4, 128)
    gemm_out<<<gg, 128>>>(Wo, bo, out);
}

// round 15
// speedup vs baseline: 1.0253x; 1.0253x over previous
#include <cuda_runtime.h>
#include <cuda_bf16.h>
#include <cuda_fp16.h>
#include <math.h>

// Problem constants
#define BB 2
#define LL 4096
#define EE 256
#define HH 8
#define DD 32
#define NPAIR 16
#define QT 64     // queries per attention CTA (4 warps x 1 m16-tile)

typedef unsigned int uint32;

// ---------------- device scratch ----------------
// Q fp16 A-frag layout (unchanged): per bh, 256 rowgroups x 2 ksteps x 4 aregs x 32 lanes.
__device__ uint32 g_qh2[16 * 65536];
// K packed layout: per bh, 64 tiles x 8 ngroups x 32 lanes x uint4{ks0p0,ks0p1,ks1p0,ks1p1}.
__device__ uint32 g_kh2[16 * 65536];
// V packed layout: per bh, 64 tiles x 4 kst2 x 2 ndp x 32 lanes x uint4{nd_lo p0,p1, nd_hi p0,p1}.
__device__ uint32 g_vh2[16 * 65536];
__device__ float g_ao[BB*HH*LL*DD];
__device__ float g_cos[LL*NPAIR];
__device__ float g_sin[LL*NPAIR];

// ---------------- helpers ----------------
__device__ __forceinline__ uint32 h2pack(float lo, float hi) {
    uint32 r;
    asm("cvt.rn.f16x2.f32 %0, %1, %2;" : "=r"(r) : "f"(hi), "f"(lo));
    return r;
}
__device__ __forceinline__ uint32 ex2h2(uint32 x) {
    uint32 r;
    asm("ex2.approx.f16x2 %0, %1;" : "=r"(r) : "r"(x));
    return r;
}
__device__ __forceinline__ void mma_f16(float* d, const uint32* a, uint32 b0, uint32 b1) {
    asm volatile(
        "mma.sync.aligned.m16n8k16.row.col.f32.f16.f16.f32 "
        "{%0,%1,%2,%3}, {%4,%5,%6,%7}, {%8,%9}, {%0,%1,%2,%3};"
        : "+f"(d[0]), "+f"(d[1]), "+f"(d[2]), "+f"(d[3])
        : "r"(a[0]), "r"(a[1]), "r"(a[2]), "r"(a[3]), "r"(b0), "r"(b1));
}
__device__ __forceinline__ void ldsm4(uint32& r0, uint32& r1, uint32& r2, uint32& r3,
                                      uint32 addr) {
    asm volatile("ldmatrix.sync.aligned.m8n8.x4.shared.b16 {%0,%1,%2,%3}, [%4];"
                 : "=r"(r0), "=r"(r1), "=r"(r2), "=r"(r3) : "r"(addr));
}
__device__ __forceinline__ void cp16(uint32 dst, const void* src) {
    asm volatile("cp.async.cg.shared.global [%0], [%1], 16;" :: "r"(dst), "l"(src));
}
__device__ __forceinline__ void split4h(float4 v, uint2& hi, uint2& lo) {
    uint32 h01 = h2pack(v.x, v.y);
    uint32 h23 = h2pack(v.z, v.w);
    float2 f01 = __half22float2(*(__half2*)&h01);
    float2 f23 = __half22float2(*(__half2*)&h23);
    uint32 l01 = h2pack(v.x - f01.x, v.y - f01.y);
    uint32 l23 = h2pack(v.z - f23.x, v.w - f23.y);
    hi = make_uint2(h01, h23);
    lo = make_uint2(l01, l23);
}

// ---------------- rope table ----------------
__global__ void rope_table_kernel() {
    int idx = blockIdx.x * blockDim.x + threadIdx.x;
    if (idx >= LL * NPAIR) return;
    int l = idx >> 4;
    int i = idx & 15;
    float t = (i < 8) ? (float)(l & 63) : (float)(l >> 6);
    int fi = i & 7;
    float freq = powf(10000.0f, -(4.0f * (float)fi) / 32.0f);
    float ang = t * freq;
    g_cos[idx] = cosf(ang);
    g_sin[idx] = sinf(ang);
}

// ---------------- fused QKV projection: fp16 mma + ldmatrix, double-buffer --
__global__ __launch_bounds__(128)
void gemm_qkv(const float* __restrict__ qi, const float* __restrict__ ki,
              const float* __restrict__ vi,
              const float* __restrict__ Wq, const float* __restrict__ Wk,
              const float* __restrict__ Wv,
              const float* __restrict__ bq, const float* __restrict__ bk,
              const float* __restrict__ bv) {
    __shared__ __align__(16) __half As[2][64 * 40];
    __shared__ __align__(16) __half Ws[2][64 * 40];

    const int mode = blockIdx.z;
    const float* A    = (mode == 0) ? qi : (mode == 1) ? ki : vi;
    const float* W    = (mode == 0) ? Wq : (mode == 1) ? Wk : Wv;
    const float* bias = (mode == 0) ? bq : (mode == 1) ? bk : bv;

    const int tid = threadIdx.x;
    const int w = tid >> 5, lane = tid & 31;
    const int quad = lane >> 2, cm = lane & 3;
    const int wm = w >> 1, wn = w & 1;
    const int m0 = blockIdx.y * 64;
    const int n0 = blockIdx.x * 64;

    float C[2][4][4];
#pragma unroll
    for (int mt = 0; mt < 2; mt++)
#pragma unroll
        for (int nt = 0; nt < 4; nt++)
#pragma unroll
            for (int j = 0; j < 4; j++) C[mt][nt][j] = 0.0f;

    const uint32 abase = (uint32)__cvta_generic_to_shared(&As[0][0]);
    const uint32 wbase = (uint32)__cvta_generic_to_shared(&Ws[0][0]);
    const int matid = lane >> 3, rowin = lane & 7;
    uint32 aAddr[2][2], bAddr[2][2];
#pragma unroll
    for (int mt = 0; mt < 2; mt++)
#pragma unroll
        for (int ks = 0; ks < 2; ks++) {
            int row = wm * 32 + mt * 16 + (matid & 1) * 8 + rowin;
            int kc = ks * 16 + (matid >> 1) * 8;
            aAddr[mt][ks] = abase + (row * 40 + kc) * 2;
        }
#pragma unroll
    for (int pr = 0; pr < 2; pr++)
#pragma unroll
        for (int ks = 0; ks < 2; ks++) {
            int n = wn * 32 + (pr * 2 + (matid >> 1)) * 8 + rowin;
            int kc = ks * 16 + (matid & 1) * 8;
            bAddr[pr][ks] = wbase + (n * 40 + kc) * 2;
        }

    float4 pa[4], pw[4];
    const int grow = tid >> 3, gc4 = tid & 7;

#define QKV_LOAD(ch)                                                          \
    {                                                                         \
        _Pragma("unroll")                                                     \
        for (int i = 0; i < 4; i++) {                                         \
            int row = grow + 16 * i;                                          \
            pa[i] = *(const float4*)(A + (size_t)(m0 + row) * 256 + (ch) * 32 + gc4 * 4); \
            pw[i] = *(const float4*)(W + (size_t)(n0 + row) * 256 + (ch) * 32 + gc4 * 4); \
        }                                                                     \
    }
#define QKV_STS(buf)                                                          \
    {                                                                         \
        _Pragma("unroll")                                                     \
        for (int i = 0; i < 4; i++) {                                         \
            int row = grow + 16 * i;                                          \
            *(uint2*)(&As[buf][row * 40 + gc4 * 4]) =                         \
                make_uint2(h2pack(pa[i].x, pa[i].y), h2pack(pa[i].z, pa[i].w)); \
            *(uint2*)(&Ws[buf][row * 40 + gc4 * 4]) =                         \
                make_uint2(h2pack(pw[i].x, pw[i].y), h2pack(pw[i].z, pw[i].w)); \
        }                                                                     \
    }

    QKV_LOAD(0);
    QKV_STS(0);
    QKV_LOAD(1);
    __syncthreads();

#pragma unroll
    for (int ch = 0; ch < 8; ch++) {
        const int buf = ch & 1;
        const uint32 boff = buf * (64 * 40 * 2);

        uint32 aF[2][2][4];
#pragma unroll
        for (int mt = 0; mt < 2; mt++)
#pragma unroll
            for (int ks = 0; ks < 2; ks++)
                ldsm4(aF[mt][ks][0], aF[mt][ks][1], aF[mt][ks][2], aF[mt][ks][3],
                      aAddr[mt][ks] + boff);
        uint32 bF[4][2][2];
#pragma unroll
        for (int pr = 0; pr < 2; pr++)
#pragma unroll
            for (int ks = 0; ks < 2; ks++) {
                uint32 r0, r1, r2, r3;
                ldsm4(r0, r1, r2, r3, bAddr[pr][ks] + boff);
                bF[2 * pr][ks][0] = r0; bF[2 * pr][ks][1] = r1;
                bF[2 * pr + 1][ks][0] = r2; bF[2 * pr + 1][ks][1] = r3;
            }

        if (ch < 7) QKV_STS(buf ^ 1);
        if (ch < 6) QKV_LOAD(ch + 2);
        __syncthreads();

#pragma unroll
        for (int ks = 0; ks < 2; ks++)
#pragma unroll
            for (int mt = 0; mt < 2; mt++)
#pragma unroll
                for (int nt = 0; nt < 4; nt++)
                    mma_f16(C[mt][nt], aF[mt][ks], bF[nt][ks][0], bF[nt][ks][1]);
    }

    // ---- epilogue: rope + packed frag-layout scatter ----
    const float QS = 0.17677669529663687f * 1.4426950408889634f;
#pragma unroll
    for (int mt = 0; mt < 2; mt++) {
        int row0 = m0 + wm * 32 + mt * 16 + quad;
#pragma unroll
        for (int nt = 0; nt < 4; nt++) {
            int col = n0 + wn * 32 + nt * 8 + 2 * cm;
            float b0 = bias[col], b1 = bias[col + 1];
#pragma unroll
            for (int half_ = 0; half_ < 2; half_++) {
                int row = row0 + half_ * 8;
                float real = C[mt][nt][half_ * 2 + 0] + b0;
                float imag = C[mt][nt][half_ * 2 + 1] + b1;
                int l = row & 4095, b = row >> 12;
                int h = col >> 5, d = col & 31;
                if (mode == 2) {
                    // V packed scatter: key=l, dims d and d+1 (same nd, d even)
                    __half* dsth = (__half*)g_vh2 + (size_t)(b * 8 + h) * 131072;
                    int tile = l >> 6, rl = l & 63;
                    int kst2 = rl >> 4, rk = rl & 15;
                    int plane = rk >> 3, t4 = (rk & 7) >> 1, lh = rk & 1;
                    int nd = d >> 3, g0 = d & 7;
                    int base = tile * 1024 + ((kst2 * 2 + (nd >> 1)) * 32) * 4
                             + (nd & 1) * 2 + plane;
                    int i0 = (base + (g0 * 4 + t4) * 4) * 2 + lh;
                    int i1 = (base + ((g0 + 1) * 4 + t4) * 4) * 2 + lh;
                    dsth[i0] = __float2half(real);
                    dsth[i1] = __float2half(imag);
                } else {
                    int p = d >> 1;
                    float cs = g_cos[l * NPAIR + p];
                    float sn = g_sin[l * NPAIR + p];
                    float out_r = real * cs - imag * sn;
                    float out_i = real * sn + imag * cs;
                    if (mode == 0) { out_r *= QS; out_i *= QS; }
                    uint32* dst = ((mode == 0) ? g_qh2 : g_kh2) + (size_t)(b * 8 + h) * 65536;
                    int ks = d >> 4, dc = d & 15;
                    uint32 packed = h2pack(out_r, out_i);
                    if (mode == 0) {
                        int rg = l >> 4, r = l & 15;
                        int areg = (r >> 3) + ((dc >> 3) << 1);
                        int ln = (r & 7) * 4 + ((dc & 7) >> 1);
                        dst[((rg * 2 + ks) * 4 + areg) * 32 + ln] = packed;
                    } else {
                        // K packed scatter
                        int tile = l >> 6, ng = (l & 63) >> 3;
                        int plane = dc >> 3;
                        int ln = (l & 7) * 4 + ((dc & 7) >> 1);
                        dst[tile * 1024 + (ng * 32 + ln) * 4 + ks * 2 + plane] = packed;
                    }
                }
            }
        }
    }
}

// ---------------- output projection: fp16 x2 split, double-buffer ----------
__global__ __launch_bounds__(128, 4)
void gemm_out(const float* __restrict__ W, const float* __restrict__ bias,
              float* __restrict__ out) {
    __shared__ __align__(16) __half Ah[2][64 * 40];
    __shared__ __align__(16) __half Al[2][64 * 40];
    __shared__ __align__(16) __half Wh[2][64 * 40];
    __shared__ __align__(16) __half Wl[2][64 * 40];

    const int tid = threadIdx.x;
    const int w = tid >> 5, lane = tid & 31;
    const int quad = lane >> 2, cm = lane & 3;
    const int wm = w >> 1, wn = w & 1;
    const int m0 = blockIdx.y * 64;
    const int n0 = blockIdx.x * 64;

    float C[2][4][4];
#pragma unroll
    for (int mt = 0; mt < 2; mt++)
#pragma unroll
        for (int nt = 0; nt < 4; nt++)
#pragma unroll
            for (int j = 0; j < 4; j++) C[mt][nt][j] = 0.0f;

    const uint32 ahb = (uint32)__cvta_generic_to_shared(&Ah[0][0]);
    const uint32 alb = (uint32)__cvta_generic_to_shared(&Al[0][0]);
    const uint32 whb = (uint32)__cvta_generic_to_shared(&Wh[0][0]);
    const uint32 wlb = (uint32)__cvta_generic_to_shared(&Wl[0][0]);
    const int matid = lane >> 3, rowin = lane & 7;
    uint32 aOff[2][2], bOff[2][2];
#pragma unroll
    for (int mt = 0; mt < 2; mt++)
#pragma unroll
        for (int ks = 0; ks < 2; ks++) {
            int row = wm * 32 + mt * 16 + (matid & 1) * 8 + rowin;
            int kc = ks * 16 + (matid >> 1) * 8;
            aOff[mt][ks] = (row * 40 + kc) * 2;
        }
#pragma unroll
    for (int pr = 0; pr < 2; pr++)
#pragma unroll
        for (int ks = 0; ks < 2; ks++) {
            int n = wn * 32 + (pr * 2 + (matid >> 1)) * 8 + rowin;
            int kc = ks * 16 + (matid & 1) * 8;
            bOff[pr][ks] = (n * 40 + kc) * 2;
        }

    float4 pa[4], pw[4];
    const int grow = tid >> 3, gc4 = tid & 7;

#define OUT_LOAD(ch)                                                          \
    {                                                                         \
        _Pragma("unroll")                                                     \
        for (int i = 0; i < 4; i++) {                                         \
            int row = grow + 16 * i;                                          \
            int m = m0 + row;                                                 \
            int b = m >> 12, l = m & 4095;                                    \
            pa[i] = *(const float4*)(g_ao + (((size_t)(b * 8 + (ch)) * 4096) + l) * 32 + gc4 * 4); \
            pw[i] = *(const float4*)(W + (size_t)(n0 + row) * 256 + (ch) * 32 + gc4 * 4); \
        }                                                                     \
    }
#define OUT_STS(buf)                                                          \
    {                                                                         \
        _Pragma("unroll")                                                     \
        for (int i = 0; i < 4; i++) {                                         \
            int row = grow + 16 * i;                                          \
            uint2 hi, lo;                                                     \
            split4h(pa[i], hi, lo);                                           \
            *(uint2*)(&Ah[buf][row * 40 + gc4 * 4]) = hi;                     \
            *(uint2*)(&Al[buf][row * 40 + gc4 * 4]) = lo;                     \
            split4h(pw[i], hi, lo);                                           \
            *(uint2*)(&Wh[buf][row * 40 + gc4 * 4]) = hi;                     \
            *(uint2*)(&Wl[buf][row * 40 + gc4 * 4]) = lo;                     \
        }                                                                     \
    }

    OUT_LOAD(0);
    OUT_STS(0);
    OUT_LOAD(1);
    __syncthreads();

#pragma unroll
    for (int ch = 0; ch < 8; ch++) {
        const int buf = ch & 1;
        const uint32 boff = buf * (64 * 40 * 2);

        uint32 aH[2][2][4], aL[2][2][4];
#pragma unroll
        for (int mt = 0; mt < 2; mt++)
#pragma unroll
            for (int ks = 0; ks < 2; ks++) {
                ldsm4(aH[mt][ks][0], aH[mt][ks][1], aH[mt][ks][2], aH[mt][ks][3],
                      ahb + aOff[mt][ks] + boff);
                ldsm4(aL[mt][ks][0], aL[mt][ks][1], aL[mt][ks][2], aL[mt][ks][3],
                      alb + aOff[mt][ks] + boff);
            }
        uint32 bH[4][2][2], bL[4][2][2];
#pragma unroll
        for (int pr = 0; pr < 2; pr++)
#pragma unroll
            for (int ks = 0; ks < 2; ks++) {
                uint32 r0, r1, r2, r3;
                ldsm4(r0, r1, r2, r3, whb + bOff[pr][ks] + boff);
                bH[2 * pr][ks][0] = r0; bH[2 * pr][ks][1] = r1;
                bH[2 * pr + 1][ks][0] = r2; bH[2 * pr + 1][ks][1] = r3;
                ldsm4(r0, r1, r2, r3, wlb + bOff[pr][ks] + boff);
                bL[2 * pr][ks][0] = r0; bL[2 * pr][ks][1] = r1;
                bL[2 * pr + 1][ks][0] = r2; bL[2 * pr + 1][ks][1] = r3;
            }

        if (ch < 7) OUT_STS(buf ^ 1);
        if (ch < 6) OUT_LOAD(ch + 2);
        __syncthreads();

#pragma unroll
        for (int ks = 0; ks < 2; ks++)
#pragma unroll
            for (int mt = 0; mt < 2; mt++)
#pragma unroll
                for (int nt = 0; nt < 4; nt++) {
                    mma_f16(C[mt][nt], aH[mt][ks], bH[nt][ks][0], bH[nt][ks][1]);
                    mma_f16(C[mt][nt], aL[mt][ks], bH[nt][ks][0], bH[nt][ks][1]);
                    mma_f16(C[mt][nt], aH[mt][ks], bL[nt][ks][0], bL[nt][ks][1]);
                }
    }

#pragma unroll
    for (int mt = 0; mt < 2; mt++) {
        int row0 = m0 + wm * 32 + mt * 16 + quad;
#pragma unroll
        for (int nt = 0; nt < 4; nt++) {
            int col = n0 + wn * 32 + nt * 8 + 2 * cm;
            float b0 = bias[col], b1 = bias[col + 1];
#pragma unroll
            for (int half_ = 0; half_ < 2; half_++) {
                int row = row0 + half_ * 8;
                float real = C[mt][nt][half_ * 2 + 0] + b0;
                float imag = C[mt][nt][half_ * 2 + 1] + b1;
                *(float2*)(out + (size_t)row * 256 + col) = make_float2(real, imag);
            }
        }
    }
}

// ---------------- flash attention: QT=64 balanced, packed LDS.128 ---------
__global__ __launch_bounds__(128, 7)
void attn_mma() {
    __shared__ __align__(16) uint32 sK[2][1024];
    __shared__ __align__(16) uint32 sV[2][1024];

    const int tid = threadIdx.x;
    const int w = tid >> 5;
    const int lane = tid & 31;
    const int quad = lane >> 2;
    const int cm = lane & 3;
    const int bh = blockIdx.y;
    const int q0 = blockIdx.x * QT;
    const uint32 ONES2 = 0x3C003C00u;

    const uint32* Q2 = g_qh2 + (size_t)bh * 65536;
    const uint32* K2 = g_kh2 + (size_t)bh * 65536;
    const uint32* V2 = g_vh2 + (size_t)bh * 65536;

    // ---- Q fp16 A-fragments (1 m-tile per warp) ----
    uint32 qf[2][4];
    {
        int rg = (q0 >> 4) + w;
#pragma unroll
        for (int ks = 0; ks < 2; ks++)
#pragma unroll
            for (int ar = 0; ar < 4; ar++)
                qf[ks][ar] = Q2[((rg * 2 + ks) * 4 + ar) * 32 + lane];
    }

    float O[4][4];
#pragma unroll
    for (int nd = 0; nd < 4; nd++)
#pragma unroll
        for (int j = 0; j < 4; j++) O[nd][j] = 0.0f;

    float Lac[4] = {0.f, 0.f, 0.f, 0.f};

    const uint32 sKb = (uint32)__cvta_generic_to_shared(&sK[0][0]);
    const uint32 sVb = (uint32)__cvta_generic_to_shared(&sV[0][0]);

    {
        const float4* Kg = (const float4*)K2;
        const float4* Vg = (const float4*)V2;
#pragma unroll
        for (int i = 0; i < 2; i++) {
            cp16(sKb + (tid + 128 * i) * 16, Kg + tid + 128 * i);
            cp16(sVb + (tid + 128 * i) * 16, Vg + tid + 128 * i);
        }
        asm volatile("cp.async.commit_group;");
    }

    for (int t = 0; t < LL / 64; t++) {
        const int buf = t & 1;
        if (t + 1 < LL / 64) {
            const float4* Kg = (const float4*)(K2 + (size_t)(t + 1) * 1024);
            const float4* Vg = (const float4*)(V2 + (size_t)(t + 1) * 1024);
            uint32 dK = sKb + (buf ^ 1) * 4096;
            uint32 dV = sVb + (buf ^ 1) * 4096;
#pragma unroll
            for (int i = 0; i < 2; i++) {
                cp16(dK + (tid + 128 * i) * 16, Kg + tid + 128 * i);
                cp16(dV + (tid + 128 * i) * 16, Vg + tid + 128 * i);
            }
            asm volatile("cp.async.commit_group;");
            asm volatile("cp.async.wait_group 1;");
        } else {
            asm volatile("cp.async.wait_group 0;");
        }
        __syncthreads();

        const uint4* Kt = (const uint4*)sK[buf];
        const uint4* Vt = (const uint4*)sV[buf];

        uint32 aP[4];

#pragma unroll
        for (int n = 0; n < 8; n++) {
            uint4 kb = Kt[n * 32 + lane];          // {ks0p0, ks0p1, ks1p0, ks1p1}
            float S[4] = {0.f, 0.f, 0.f, 0.f};
            mma_f16(S, qf[0], kb.x, kb.y);
            mma_f16(S, qf[1], kb.z, kb.w);

            const int off = (n & 1) * 2;
            aP[off + 0] = ex2h2(h2pack(S[0], S[1]));
            aP[off + 1] = ex2h2(h2pack(S[2], S[3]));

            if (n & 1) {
                const int kst2 = n >> 1;
                mma_f16(Lac, aP, ONES2, ONES2);
                uint4 v01 = Vt[(kst2 * 2 + 0) * 32 + lane];  // nd0, nd1
                uint4 v23 = Vt[(kst2 * 2 + 1) * 32 + lane];  // nd2, nd3
                mma_f16(O[0], aP, v01.x, v01.y);
                mma_f16(O[1], aP, v01.z, v01.w);
                mma_f16(O[2], aP, v23.x, v23.y);
                mma_f16(O[3], aP, v23.z, v23.w);
            }
        }
        __syncthreads();
    }

    // ---- epilogue ----
    float* aob = g_ao + (size_t)bh * LL * DD;
    float i0 = 1.0f / Lac[0];
    float i1 = 1.0f / Lac[2];
    int qrow = q0 + w * 16 + quad;
#pragma unroll
    for (int nd = 0; nd < 4; nd++) {
        float2 v0 = make_float2(O[nd][0] * i0, O[nd][1] * i0);
        float2 v1 = make_float2(O[nd][2] * i1, O[nd][3] * i1);
        *(float2*)(aob + (size_t)qrow * DD + 8 * nd + 2 * cm) = v0;
        *(float2*)(aob + (size_t)(qrow + 8) * DD + 8 * nd + 2 * cm) = v1;
    }
}

// ---------------- launcher ----------------
extern "C" void kernel_launch(void* const* d_in, const int* in_sizes, int n_in,
                              void* d_out, int out_size) {
    const float* q  = (const float*)d_in[0];
    const float* k  = (const float*)d_in[1];
    const float* v  = (const float*)d_in[2];
    const float* Wq = (const float*)d_in[3];
    const float* bq = (const float*)d_in[4];
    const float* Wk = (const float*)d_in[5];
    const float* bk = (const float*)d_in[6];
    const float* Wv = (const float*)d_in[7];
    const float* bv = (const float*)d_in[8];
    const float* Wo = (const float*)d_in[9];
    const float* bo = (const float*)d_in[10];
    float* out = (float*)d_out;

    rope_table_kernel<<<(LL * NPAIR + 255) / 256, 256>>>();

    dim3 g3(EE / 64, (BB * LL) / 64, 3);  // (4, 128, 3) — fused Q/K/V
    gemm_qkv<<<g3, 128>>>(q, k, v, Wq, Wk, Wv, bq, bk, bv);

    attn_mma<<<dim3(LL / QT, BB * HH), 128>>>();   // (64, 16)

    dim3 gg(EE / 64, (BB * LL) / 64);  // (4, 128)
    gemm_out<<<gg, 128>>>(Wo, bo, out);
}

// round 16
// speedup vs baseline: 1.0258x; 1.0005x over previous
#include <cuda_runtime.h>
#include <cuda_bf16.h>
#include <cuda_fp16.h>
#include <math.h>

// Problem constants
#define BB 2
#define LL 4096
#define EE 256
#define HH 8
#define DD 32
#define NPAIR 16
#define QT 64     // queries per attention CTA (4 warps x 1 m16-tile)

typedef unsigned int uint32;

// ---------------- device scratch ----------------
// Q fp16 A-frag layout: per bh, 256 rowgroups x 2 ksteps x 4 aregs x 32 lanes.
__device__ uint32 g_qh2[16 * 65536];
// K packed layout: per bh, 64 tiles x 8 ngroups x 32 lanes x uint4{ks0p0,ks0p1,ks1p0,ks1p1}.
__device__ uint32 g_kh2[16 * 65536];
// V packed layout: per bh, 64 tiles x 4 kst2 x 2 ndp x 32 lanes x uint4.
__device__ uint32 g_vh2[16 * 65536];
__device__ float g_ao[BB*HH*LL*DD];
__device__ float g_cos[LL*NPAIR];
__device__ float g_sin[LL*NPAIR];

// ---------------- helpers ----------------
__device__ __forceinline__ uint32 h2pack(float lo, float hi) {
    uint32 r;
    asm("cvt.rn.f16x2.f32 %0, %1, %2;" : "=r"(r) : "f"(hi), "f"(lo));
    return r;
}
__device__ __forceinline__ uint32 ex2h2(uint32 x) {
    uint32 r;
    asm("ex2.approx.f16x2 %0, %1;" : "=r"(r) : "r"(x));
    return r;
}
__device__ __forceinline__ void mma_f16(float* d, const uint32* a, uint32 b0, uint32 b1) {
    asm volatile(
        "mma.sync.aligned.m16n8k16.row.col.f32.f16.f16.f32 "
        "{%0,%1,%2,%3}, {%4,%5,%6,%7}, {%8,%9}, {%0,%1,%2,%3};"
        : "+f"(d[0]), "+f"(d[1]), "+f"(d[2]), "+f"(d[3])
        : "r"(a[0]), "r"(a[1]), "r"(a[2]), "r"(a[3]), "r"(b0), "r"(b1));
}
__device__ __forceinline__ void ldsm4(uint32& r0, uint32& r1, uint32& r2, uint32& r3,
                                      uint32 addr) {
    asm volatile("ldmatrix.sync.aligned.m8n8.x4.shared.b16 {%0,%1,%2,%3}, [%4];"
                 : "=r"(r0), "=r"(r1), "=r"(r2), "=r"(r3) : "r"(addr));
}
__device__ __forceinline__ void cp16(uint32 dst, const void* src) {
    asm volatile("cp.async.cg.shared.global [%0], [%1], 16;" :: "r"(dst), "l"(src));
}
__device__ __forceinline__ void split4h(float4 v, uint2& hi, uint2& lo) {
    uint32 h01 = h2pack(v.x, v.y);
    uint32 h23 = h2pack(v.z, v.w);
    float2 f01 = __half22float2(*(__half2*)&h01);
    float2 f23 = __half22float2(*(__half2*)&h23);
    uint32 l01 = h2pack(v.x - f01.x, v.y - f01.y);
    uint32 l23 = h2pack(v.z - f23.x, v.w - f23.y);
    hi = make_uint2(h01, h23);
    lo = make_uint2(l01, l23);
}

// ---------------- rope table ----------------
__global__ void rope_table_kernel() {
    int idx = blockIdx.x * blockDim.x + threadIdx.x;
    if (idx >= LL * NPAIR) return;
    int l = idx >> 4;
    int i = idx & 15;
    float t = (i < 8) ? (float)(l & 63) : (float)(l >> 6);
    int fi = i & 7;
    float freq = powf(10000.0f, -(4.0f * (float)fi) / 32.0f);
    float ang = t * freq;
    g_cos[idx] = cosf(ang);
    g_sin[idx] = sinf(ang);
}

// ---------------- fused QKV projection: fp16 mma + ldmatrix ----------------
// Epilogue scatters into smem, then 512 coalesced STG.128 to global.
__global__ __launch_bounds__(128)
void gemm_qkv(const float* __restrict__ qi, const float* __restrict__ ki,
              const float* __restrict__ vi,
              const float* __restrict__ Wq, const float* __restrict__ Wk,
              const float* __restrict__ Wv,
              const float* __restrict__ bq, const float* __restrict__ bk,
              const float* __restrict__ bv) {
    __shared__ __align__(16) __half As[2][64 * 40];
    __shared__ __align__(16) __half Ws[2][64 * 40];
    __shared__ __align__(16) uint32 ebuf[2048];   // 8KB epilogue staging

    const int mode = blockIdx.z;
    const float* A    = (mode == 0) ? qi : (mode == 1) ? ki : vi;
    const float* W    = (mode == 0) ? Wq : (mode == 1) ? Wk : Wv;
    const float* bias = (mode == 0) ? bq : (mode == 1) ? bk : bv;

    const int tid = threadIdx.x;
    const int w = tid >> 5, lane = tid & 31;
    const int quad = lane >> 2, cm = lane & 3;
    const int wm = w >> 1, wn = w & 1;
    const int m0 = blockIdx.y * 64;
    const int n0 = blockIdx.x * 64;

    float C[2][4][4];
#pragma unroll
    for (int mt = 0; mt < 2; mt++)
#pragma unroll
        for (int nt = 0; nt < 4; nt++)
#pragma unroll
            for (int j = 0; j < 4; j++) C[mt][nt][j] = 0.0f;

    const uint32 abase = (uint32)__cvta_generic_to_shared(&As[0][0]);
    const uint32 wbase = (uint32)__cvta_generic_to_shared(&Ws[0][0]);
    const int matid = lane >> 3, rowin = lane & 7;
    uint32 aAddr[2][2], bAddr[2][2];
#pragma unroll
    for (int mt = 0; mt < 2; mt++)
#pragma unroll
        for (int ks = 0; ks < 2; ks++) {
            int row = wm * 32 + mt * 16 + (matid & 1) * 8 + rowin;
            int kc = ks * 16 + (matid >> 1) * 8;
            aAddr[mt][ks] = abase + (row * 40 + kc) * 2;
        }
#pragma unroll
    for (int pr = 0; pr < 2; pr++)
#pragma unroll
        for (int ks = 0; ks < 2; ks++) {
            int n = wn * 32 + (pr * 2 + (matid >> 1)) * 8 + rowin;
            int kc = ks * 16 + (matid & 1) * 8;
            bAddr[pr][ks] = wbase + (n * 40 + kc) * 2;
        }

    float4 pa[4], pw[4];
    const int grow = tid >> 3, gc4 = tid & 7;

#define QKV_LOAD(ch)                                                          \
    {                                                                         \
        _Pragma("unroll")                                                     \
        for (int i = 0; i < 4; i++) {                                         \
            int row = grow + 16 * i;                                          \
            pa[i] = *(const float4*)(A + (size_t)(m0 + row) * 256 + (ch) * 32 + gc4 * 4); \
            pw[i] = *(const float4*)(W + (size_t)(n0 + row) * 256 + (ch) * 32 + gc4 * 4); \
        }                                                                     \
    }
#define QKV_STS(buf)                                                          \
    {                                                                         \
        _Pragma("unroll")                                                     \
        for (int i = 0; i < 4; i++) {                                         \
            int row = grow + 16 * i;                                          \
            *(uint2*)(&As[buf][row * 40 + gc4 * 4]) =                         \
                make_uint2(h2pack(pa[i].x, pa[i].y), h2pack(pa[i].z, pa[i].w)); \
            *(uint2*)(&Ws[buf][row * 40 + gc4 * 4]) =                         \
                make_uint2(h2pack(pw[i].x, pw[i].y), h2pack(pw[i].z, pw[i].w)); \
        }                                                                     \
    }

    QKV_LOAD(0);
    QKV_STS(0);
    QKV_LOAD(1);
    __syncthreads();

#pragma unroll
    for (int ch = 0; ch < 8; ch++) {
        const int buf = ch & 1;
        const uint32 boff = buf * (64 * 40 * 2);

        uint32 aF[2][2][4];
#pragma unroll
        for (int mt = 0; mt < 2; mt++)
#pragma unroll
            for (int ks = 0; ks < 2; ks++)
                ldsm4(aF[mt][ks][0], aF[mt][ks][1], aF[mt][ks][2], aF[mt][ks][3],
                      aAddr[mt][ks] + boff);
        uint32 bF[4][2][2];
#pragma unroll
        for (int pr = 0; pr < 2; pr++)
#pragma unroll
            for (int ks = 0; ks < 2; ks++) {
                uint32 r0, r1, r2, r3;
                ldsm4(r0, r1, r2, r3, bAddr[pr][ks] + boff);
                bF[2 * pr][ks][0] = r0; bF[2 * pr][ks][1] = r1;
                bF[2 * pr + 1][ks][0] = r2; bF[2 * pr + 1][ks][1] = r3;
            }

        if (ch < 7) QKV_STS(buf ^ 1);
        if (ch < 6) QKV_LOAD(ch + 2);
        __syncthreads();

#pragma unroll
        for (int ks = 0; ks < 2; ks++)
#pragma unroll
            for (int mt = 0; mt < 2; mt++)
#pragma unroll
                for (int nt = 0; nt < 4; nt++)
                    mma_f16(C[mt][nt], aF[mt][ks], bF[nt][ks][0], bF[nt][ks][1]);
    }

    // ---- epilogue: rope + scatter into smem, then coalesced global copy ----
    const float QS = 0.17677669529663687f * 1.4426950408889634f;
    __half* ebufh = (__half*)ebuf;
#pragma unroll
    for (int mt = 0; mt < 2; mt++) {
        int row0 = m0 + wm * 32 + mt * 16 + quad;
#pragma unroll
        for (int nt = 0; nt < 4; nt++) {
            int col = n0 + wn * 32 + nt * 8 + 2 * cm;
            float b0 = bias[col], b1 = bias[col + 1];
            int hl = (col & 63) >> 5;       // head-local index (0/1)
            int d = col & 31;
#pragma unroll
            for (int half_ = 0; half_ < 2; half_++) {
                int row = row0 + half_ * 8;
                float real = C[mt][nt][half_ * 2 + 0] + b0;
                float imag = C[mt][nt][half_ * 2 + 1] + b1;
                int lloc = row & 63;        // local row (m0 is 64-aligned)
                if (mode == 2) {
                    int kst2 = lloc >> 4, rk = lloc & 15;
                    int plane = rk >> 3, t4 = (rk & 7) >> 1, lh = rk & 1;
                    int nd = d >> 3, g0 = d & 7;
                    int baseloc = ((kst2 * 2 + (nd >> 1)) * 32) * 4 + (nd & 1) * 2 + plane;
                    int i0 = (baseloc + (g0 * 4 + t4) * 4) * 2 + lh;
                    int i1 = (baseloc + ((g0 + 1) * 4 + t4) * 4) * 2 + lh;
                    ebufh[hl * 2048 + i0] = __float2half(real);
                    ebufh[hl * 2048 + i1] = __float2half(imag);
                } else {
                    int l = row & 4095;
                    int p = d >> 1;
                    float cs = g_cos[l * NPAIR + p];
                    float sn = g_sin[l * NPAIR + p];
                    float out_r = real * cs - imag * sn;
                    float out_i = real * sn + imag * cs;
                    if (mode == 0) { out_r *= QS; out_i *= QS; }
                    uint32 packed = h2pack(out_r, out_i);
                    int ks = d >> 4, dc = d & 15;
                    if (mode == 0) {
                        int rg_local = lloc >> 4, r = lloc & 15;
                        int areg = (r >> 3) + ((dc >> 3) << 1);
                        int ln = (r & 7) * 4 + ((dc & 7) >> 1);
                        ebuf[hl * 1024 + ((rg_local * 2 + ks) * 4 + areg) * 32 + ln] = packed;
                    } else {
                        int ng = lloc >> 3;
                        int plane = dc >> 3;
                        int ln = (lloc & 7) * 4 + ((dc & 7) >> 1);
                        ebuf[hl * 1024 + (ng * 32 + ln) * 4 + ks * 2 + plane] = packed;
                    }
                }
            }
        }
    }
    __syncthreads();

    // coalesced copy: 2 heads x 4KB contiguous blocks
    {
        int b = m0 >> 12;
        int h0 = n0 >> 5;
        uint32* garr = (mode == 0) ? g_qh2 : (mode == 1) ? g_kh2 : g_vh2;
        int blockbase = (mode == 0) ? (((m0 & 4095) >> 4) * 256)
                                    : (((m0 & 4095) >> 6) * 1024);
#pragma unroll
        for (int i = 0; i < 4; i++) {
            int slot = tid + 128 * i;        // 0..511
            int hl = slot >> 8, off = slot & 255;
            uint4 v = ((const uint4*)ebuf)[hl * 256 + off];
            size_t gb = (size_t)((b * 8 + h0 + hl)) * 65536 + blockbase;
            *(uint4*)(garr + gb + off * 4) = v;
        }
    }
}

// ---------------- output projection: fp16 x2 split, double-buffer ----------
__global__ __launch_bounds__(128, 4)
void gemm_out(const float* __restrict__ W, const float* __restrict__ bias,
              float* __restrict__ out) {
    __shared__ __align__(16) __half Ah[2][64 * 40];
    __shared__ __align__(16) __half Al[2][64 * 40];
    __shared__ __align__(16) __half Wh[2][64 * 40];
    __shared__ __align__(16) __half Wl[2][64 * 40];

    const int tid = threadIdx.x;
    const int w = tid >> 5, lane = tid & 31;
    const int quad = lane >> 2, cm = lane & 3;
    const int wm = w >> 1, wn = w & 1;
    const int m0 = blockIdx.y * 64;
    const int n0 = blockIdx.x * 64;

    float C[2][4][4];
#pragma unroll
    for (int mt = 0; mt < 2; mt++)
#pragma unroll
        for (int nt = 0; nt < 4; nt++)
#pragma unroll
            for (int j = 0; j < 4; j++) C[mt][nt][j] = 0.0f;

    const uint32 ahb = (uint32)__cvta_generic_to_shared(&Ah[0][0]);
    const uint32 alb = (uint32)__cvta_generic_to_shared(&Al[0][0]);
    const uint32 whb = (uint32)__cvta_generic_to_shared(&Wh[0][0]);
    const uint32 wlb = (uint32)__cvta_generic_to_shared(&Wl[0][0]);
    const int matid = lane >> 3, rowin = lane & 7;
    uint32 aOff[2][2], bOff[2][2];
#pragma unroll
    for (int mt = 0; mt < 2; mt++)
#pragma unroll
        for (int ks = 0; ks < 2; ks++) {
            int row = wm * 32 + mt * 16 + (matid & 1) * 8 + rowin;
            int kc = ks * 16 + (matid >> 1) * 8;
            aOff[mt][ks] = (row * 40 + kc) * 2;
        }
#pragma unroll
    for (int pr = 0; pr < 2; pr++)
#pragma unroll
        for (int ks = 0; ks < 2; ks++) {
            int n = wn * 32 + (pr * 2 + (matid >> 1)) * 8 + rowin;
            int kc = ks * 16 + (matid & 1) * 8;
            bOff[pr][ks] = (n * 40 + kc) * 2;
        }

    float4 pa[4], pw[4];
    const int grow = tid >> 3, gc4 = tid & 7;

#define OUT_LOAD(ch)                                                          \
    {                                                                         \
        _Pragma("unroll")                                                     \
        for (int i = 0; i < 4; i++) {                                         \
            int row = grow + 16 * i;                                          \
            int m = m0 + row;                                                 \
            int b = m >> 12, l = m & 4095;                                    \
            pa[i] = *(const float4*)(g_ao + (((size_t)(b * 8 + (ch)) * 4096) + l) * 32 + gc4 * 4); \
            pw[i] = *(const float4*)(W + (size_t)(n0 + row) * 256 + (ch) * 32 + gc4 * 4); \
        }                                                                     \
    }
#define OUT_STS(buf)                                                          \
    {                                                                         \
        _Pragma("unroll")                                                     \
        for (int i = 0; i < 4; i++) {                                         \
            int row = grow + 16 * i;                                          \
            uint2 hi, lo;                                                     \
            split4h(pa[i], hi, lo);                                           \
            *(uint2*)(&Ah[buf][row * 40 + gc4 * 4]) = hi;                     \
            *(uint2*)(&Al[buf][row * 40 + gc4 * 4]) = lo;                     \
            split4h(pw[i], hi, lo);                                           \
            *(uint2*)(&Wh[buf][row * 40 + gc4 * 4]) = hi;                     \
            *(uint2*)(&Wl[buf][row * 40 + gc4 * 4]) = lo;                     \
        }                                                                     \
    }

    OUT_LOAD(0);
    OUT_STS(0);
    OUT_LOAD(1);
    __syncthreads();

#pragma unroll
    for (int ch = 0; ch < 8; ch++) {
        const int buf = ch & 1;
        const uint32 boff = buf * (64 * 40 * 2);

        uint32 aH[2][2][4], aL[2][2][4];
#pragma unroll
        for (int mt = 0; mt < 2; mt++)
#pragma unroll
            for (int ks = 0; ks < 2; ks++) {
                ldsm4(aH[mt][ks][0], aH[mt][ks][1], aH[mt][ks][2], aH[mt][ks][3],
                      ahb + aOff[mt][ks] + boff);
                ldsm4(aL[mt][ks][0], aL[mt][ks][1], aL[mt][ks][2], aL[mt][ks][3],
                      alb + aOff[mt][ks] + boff);
            }
        uint32 bH[4][2][2], bL[4][2][2];
#pragma unroll
        for (int pr = 0; pr < 2; pr++)
#pragma unroll
            for (int ks = 0; ks < 2; ks++) {
                uint32 r0, r1, r2, r3;
                ldsm4(r0, r1, r2, r3, whb + bOff[pr][ks] + boff);
                bH[2 * pr][ks][0] = r0; bH[2 * pr][ks][1] = r1;
                bH[2 * pr + 1][ks][0] = r2; bH[2 * pr + 1][ks][1] = r3;
                ldsm4(r0, r1, r2, r3, wlb + bOff[pr][ks] + boff);
                bL[2 * pr][ks][0] = r0; bL[2 * pr][ks][1] = r1;
                bL[2 * pr + 1][ks][0] = r2; bL[2 * pr + 1][ks][1] = r3;
            }

        if (ch < 7) OUT_STS(buf ^ 1);
        if (ch < 6) OUT_LOAD(ch + 2);
        __syncthreads();

#pragma unroll
        for (int ks = 0; ks < 2; ks++)
#pragma unroll
            for (int mt = 0; mt < 2; mt++)
#pragma unroll
                for (int nt = 0; nt < 4; nt++) {
                    mma_f16(C[mt][nt], aH[mt][ks], bH[nt][ks][0], bH[nt][ks][1]);
                    mma_f16(C[mt][nt], aL[mt][ks], bH[nt][ks][0], bH[nt][ks][1]);
                    mma_f16(C[mt][nt], aH[mt][ks], bL[nt][ks][0], bL[nt][ks][1]);
                }
    }

#pragma unroll
    for (int mt = 0; mt < 2; mt++) {
        int row0 = m0 + wm * 32 + mt * 16 + quad;
#pragma unroll
        for (int nt = 0; nt < 4; nt++) {
            int col = n0 + wn * 32 + nt * 8 + 2 * cm;
            float b0 = bias[col], b1 = bias[col + 1];
#pragma unroll
            for (int half_ = 0; half_ < 2; half_++) {
                int row = row0 + half_ * 8;
                float real = C[mt][nt][half_ * 2 + 0] + b0;
                float imag = C[mt][nt][half_ * 2 + 1] + b1;
                *(float2*)(out + (size_t)row * 256 + col) = make_float2(real, imag);
            }
        }
    }
}

// ---------------- flash attention: QT=64 balanced, packed LDS.128 ---------
__global__ __launch_bounds__(128, 7)
void attn_mma() {
    __shared__ __align__(16) uint32 sK[2][1024];
    __shared__ __align__(16) uint32 sV[2][1024];

    const int tid = threadIdx.x;
    const int w = tid >> 5;
    const int lane = tid & 31;
    const int quad = lane >> 2;
    const int cm = lane & 3;
    const int bh = blockIdx.y;
    const int q0 = blockIdx.x * QT;
    const uint32 ONES2 = 0x3C003C00u;

    const uint32* Q2 = g_qh2 + (size_t)bh * 65536;
    const uint32* K2 = g_kh2 + (size_t)bh * 65536;
    const uint32* V2 = g_vh2 + (size_t)bh * 65536;

    uint32 qf[2][4];
    {
        int rg = (q0 >> 4) + w;
#pragma unroll
        for (int ks = 0; ks < 2; ks++)
#pragma unroll
            for (int ar = 0; ar < 4; ar++)
                qf[ks][ar] = Q2[((rg * 2 + ks) * 4 + ar) * 32 + lane];
    }

    float O[4][4];
#pragma unroll
    for (int nd = 0; nd < 4; nd++)
#pragma unroll
        for (int j = 0; j < 4; j++) O[nd][j] = 0.0f;

    float Lac[4] = {0.f, 0.f, 0.f, 0.f};

    const uint32 sKb = (uint32)__cvta_generic_to_shared(&sK[0][0]);
    const uint32 sVb = (uint32)__cvta_generic_to_shared(&sV[0][0]);

    {
        const float4* Kg = (const float4*)K2;
        const float4* Vg = (const float4*)V2;
#pragma unroll
        for (int i = 0; i < 2; i++) {
            cp16(sKb + (tid + 128 * i) * 16, Kg + tid + 128 * i);
            cp16(sVb + (tid + 128 * i) * 16, Vg + tid + 128 * i);
        }
        asm volatile("cp.async.commit_group;");
    }

    for (int t = 0; t < LL / 64; t++) {
        const int buf = t & 1;
        if (t + 1 < LL / 64) {
            const float4* Kg = (const float4*)(K2 + (size_t)(t + 1) * 1024);
            const float4* Vg = (const float4*)(V2 + (size_t)(t + 1) * 1024);
            uint32 dK = sKb + (buf ^ 1) * 4096;
            uint32 dV = sVb + (buf ^ 1) * 4096;
#pragma unroll
            for (int i = 0; i < 2; i++) {
                cp16(dK + (tid + 128 * i) * 16, Kg + tid + 128 * i);
                cp16(dV + (tid + 128 * i) * 16, Vg + tid + 128 * i);
            }
            asm volatile("cp.async.commit_group;");
            asm volatile("cp.async.wait_group 1;");
        } else {
            asm volatile("cp.async.wait_group 0;");
        }
        __syncthreads();

        const uint4* Kt = (const uint4*)sK[buf];
        const uint4* Vt = (const uint4*)sV[buf];

        uint32 aP[4];

#pragma unroll
        for (int n = 0; n < 8; n++) {
            uint4 kb = Kt[n * 32 + lane];
            float S[4] = {0.f, 0.f, 0.f, 0.f};
            mma_f16(S, qf[0], kb.x, kb.y);
            mma_f16(S, qf[1], kb.z, kb.w);

            const int off = (n & 1) * 2;
            aP[off + 0] = ex2h2(h2pack(S[0], S[1]));
            aP[off + 1] = ex2h2(h2pack(S[2], S[3]));

            if (n & 1) {
                const int kst2 = n >> 1;
                mma_f16(Lac, aP, ONES2, ONES2);
                uint4 v01 = Vt[(kst2 * 2 + 0) * 32 + lane];
                uint4 v23 = Vt[(kst2 * 2 + 1) * 32 + lane];
                mma_f16(O[0], aP, v01.x, v01.y);
                mma_f16(O[1], aP, v01.z, v01.w);
                mma_f16(O[2], aP, v23.x, v23.y);
                mma_f16(O[3], aP, v23.z, v23.w);
            }
        }
        __syncthreads();
    }

    float* aob = g_ao + (size_t)bh * LL * DD;
    float i0 = 1.0f / Lac[0];
    float i1 = 1.0f / Lac[2];
    int qrow = q0 + w * 16 + quad;
#pragma unroll
    for (int nd = 0; nd < 4; nd++) {
        float2 v0 = make_float2(O[nd][0] * i0, O[nd][1] * i0);
        float2 v1 = make_float2(O[nd][2] * i1, O[nd][3] * i1);
        *(float2*)(aob + (size_t)qrow * DD + 8 * nd + 2 * cm) = v0;
        *(float2*)(aob + (size_t)(qrow + 8) * DD + 8 * nd + 2 * cm) = v1;
    }
}

// ---------------- launcher ----------------
extern "C" void kernel_launch(void* const* d_in, const int* in_sizes, int n_in,
                              void* d_out, int out_size) {
    const float* q  = (const float*)d_in[0];
    const float* k  = (const float*)d_in[1];
    const float* v  = (const float*)d_in[2];
    const float* Wq = (const float*)d_in[3];
    const float* bq = (const float*)d_in[4];
    const float* Wk = (const float*)d_in[5];
    const float* bk = (const float*)d_in[6];
    const float* Wv = (const float*)d_in[7];
    const float* bv = (const float*)d_in[8];
    const float* Wo = (const float*)d_in[9];
    const float* bo = (const float*)d_in[10];
    float* out = (float*)d_out;

    rope_table_kernel<<<(LL * NPAIR + 255) / 256, 256>>>();

    dim3 g3(EE / 64, (BB * LL) / 64, 3);  // (4, 128, 3) — fused Q/K/V
    gemm_qkv<<<g3, 128>>>(q, k, v, Wq, Wk, Wv, bq, bk, bv);

    attn_mma<<<dim3(LL / QT, BB * HH), 128>>>();   // (64, 16)

    dim3 gg(EE / 64, (BB * LL) / 64);  // (4, 128)
    gemm_out<<<gg, 128>>>(Wo, bo, out);
}

// round 17
// speedup vs baseline: 1.0466x; 1.0202x over previous
#include <cuda_runtime.h>
#include <cuda_bf16.h>
#include <cuda_fp16.h>
#include <math.h>

// Problem constants
#define BB 2
#define LL 4096
#define EE 256
#define HH 8
#define DD 32
#define NPAIR 16
#define QT 64     // queries per attention CTA (4 warps x 1 m16-tile)

typedef unsigned int uint32;

// ---------------- device scratch ----------------
// Q fp16 A-frag layout: per bh, 256 rowgroups x 2 ksteps x 4 aregs x 32 lanes.
__device__ uint32 g_qh2[16 * 65536];
// K packed layout: per bh, 64 tiles x 8 ngroups x 32 lanes x uint4{ks0p0,ks0p1,ks1p0,ks1p1}.
__device__ uint32 g_kh2[16 * 65536];
// V packed layout: per bh, 64 tiles x 4 kst2 x 2 ndp x 32 lanes x uint4.
__device__ uint32 g_vh2[16 * 65536];
// Attention output as hi/lo fp16 A-fragments for gemm_out:
// [512 rowgroups(m=8192/16)] x [16 ksteps(k=256/16)] x [32 lanes] of uint4{a0,a1,a2,a3}.
__device__ uint4 g_aoh[512 * 16 * 32];
__device__ uint4 g_aol[512 * 16 * 32];
__device__ float g_cos[LL*NPAIR];
__device__ float g_sin[LL*NPAIR];

// ---------------- helpers ----------------
__device__ __forceinline__ uint32 h2pack(float lo, float hi) {
    uint32 r;
    asm("cvt.rn.f16x2.f32 %0, %1, %2;" : "=r"(r) : "f"(hi), "f"(lo));
    return r;
}
__device__ __forceinline__ uint32 ex2h2(uint32 x) {
    uint32 r;
    asm("ex2.approx.f16x2 %0, %1;" : "=r"(r) : "r"(x));
    return r;
}
__device__ __forceinline__ void mma_f16(float* d, const uint32* a, uint32 b0, uint32 b1) {
    asm volatile(
        "mma.sync.aligned.m16n8k16.row.col.f32.f16.f16.f32 "
        "{%0,%1,%2,%3}, {%4,%5,%6,%7}, {%8,%9}, {%0,%1,%2,%3};"
        : "+f"(d[0]), "+f"(d[1]), "+f"(d[2]), "+f"(d[3])
        : "r"(a[0]), "r"(a[1]), "r"(a[2]), "r"(a[3]), "r"(b0), "r"(b1));
}
__device__ __forceinline__ void ldsm4(uint32& r0, uint32& r1, uint32& r2, uint32& r3,
                                      uint32 addr) {
    asm volatile("ldmatrix.sync.aligned.m8n8.x4.shared.b16 {%0,%1,%2,%3}, [%4];"
                 : "=r"(r0), "=r"(r1), "=r"(r2), "=r"(r3) : "r"(addr));
}
__device__ __forceinline__ void cp16(uint32 dst, const void* src) {
    asm volatile("cp.async.cg.shared.global [%0], [%1], 16;" :: "r"(dst), "l"(src));
}
__device__ __forceinline__ void split4h(float4 v, uint2& hi, uint2& lo) {
    uint32 h01 = h2pack(v.x, v.y);
    uint32 h23 = h2pack(v.z, v.w);
    float2 f01 = __half22float2(*(__half2*)&h01);
    float2 f23 = __half22float2(*(__half2*)&h23);
    uint32 l01 = h2pack(v.x - f01.x, v.y - f01.y);
    uint32 l23 = h2pack(v.z - f23.x, v.w - f23.y);
    hi = make_uint2(h01, h23);
    lo = make_uint2(l01, l23);
}
// pack two normalized values into hi half2 + lo residual half2
__device__ __forceinline__ void pack_hilo(float v0, float v1, uint32& hi, uint32& lo) {
    hi = h2pack(v0, v1);
    float2 f = __half22float2(*(__half2*)&hi);
    lo = h2pack(v0 - f.x, v1 - f.y);
}

// ---------------- rope table ----------------
__global__ void rope_table_kernel() {
    int idx = blockIdx.x * blockDim.x + threadIdx.x;
    if (idx >= LL * NPAIR) return;
    int l = idx >> 4;
    int i = idx & 15;
    float t = (i < 8) ? (float)(l & 63) : (float)(l >> 6);
    int fi = i & 7;
    float freq = powf(10000.0f, -(4.0f * (float)fi) / 32.0f);
    float ang = t * freq;
    g_cos[idx] = cosf(ang);
    g_sin[idx] = sinf(ang);
}

// ---------------- fused QKV projection: fp16 mma + ldmatrix ----------------
__global__ __launch_bounds__(128)
void gemm_qkv(const float* __restrict__ qi, const float* __restrict__ ki,
              const float* __restrict__ vi,
              const float* __restrict__ Wq, const float* __restrict__ Wk,
              const float* __restrict__ Wv,
              const float* __restrict__ bq, const float* __restrict__ bk,
              const float* __restrict__ bv) {
    __shared__ __align__(16) __half As[2][64 * 40];
    __shared__ __align__(16) __half Ws[2][64 * 40];
    __shared__ __align__(16) uint32 ebuf[2048];   // 8KB epilogue staging

    const int mode = blockIdx.z;
    const float* A    = (mode == 0) ? qi : (mode == 1) ? ki : vi;
    const float* W    = (mode == 0) ? Wq : (mode == 1) ? Wk : Wv;
    const float* bias = (mode == 0) ? bq : (mode == 1) ? bk : bv;

    const int tid = threadIdx.x;
    const int w = tid >> 5, lane = tid & 31;
    const int quad = lane >> 2, cm = lane & 3;
    const int wm = w >> 1, wn = w & 1;
    const int m0 = blockIdx.y * 64;
    const int n0 = blockIdx.x * 64;

    float C[2][4][4];
#pragma unroll
    for (int mt = 0; mt < 2; mt++)
#pragma unroll
        for (int nt = 0; nt < 4; nt++)
#pragma unroll
            for (int j = 0; j < 4; j++) C[mt][nt][j] = 0.0f;

    const uint32 abase = (uint32)__cvta_generic_to_shared(&As[0][0]);
    const uint32 wbase = (uint32)__cvta_generic_to_shared(&Ws[0][0]);
    const int matid = lane >> 3, rowin = lane & 7;
    uint32 aAddr[2][2], bAddr[2][2];
#pragma unroll
    for (int mt = 0; mt < 2; mt++)
#pragma unroll
        for (int ks = 0; ks < 2; ks++) {
            int row = wm * 32 + mt * 16 + (matid & 1) * 8 + rowin;
            int kc = ks * 16 + (matid >> 1) * 8;
            aAddr[mt][ks] = abase + (row * 40 + kc) * 2;
        }
#pragma unroll
    for (int pr = 0; pr < 2; pr++)
#pragma unroll
        for (int ks = 0; ks < 2; ks++) {
            int n = wn * 32 + (pr * 2 + (matid >> 1)) * 8 + rowin;
            int kc = ks * 16 + (matid & 1) * 8;
            bAddr[pr][ks] = wbase + (n * 40 + kc) * 2;
        }

    float4 pa[4], pw[4];
    const int grow = tid >> 3, gc4 = tid & 7;

#define QKV_LOAD(ch)                                                          \
    {                                                                         \
        _Pragma("unroll")                                                     \
        for (int i = 0; i < 4; i++) {                                         \
            int row = grow + 16 * i;                                          \
            pa[i] = *(const float4*)(A + (size_t)(m0 + row) * 256 + (ch) * 32 + gc4 * 4); \
            pw[i] = *(const float4*)(W + (size_t)(n0 + row) * 256 + (ch) * 32 + gc4 * 4); \
        }                                                                     \
    }
#define QKV_STS(buf)                                                          \
    {                                                                         \
        _Pragma("unroll")                                                     \
        for (int i = 0; i < 4; i++) {                                         \
            int row = grow + 16 * i;                                          \
            *(uint2*)(&As[buf][row * 40 + gc4 * 4]) =                         \
                make_uint2(h2pack(pa[i].x, pa[i].y), h2pack(pa[i].z, pa[i].w)); \
            *(uint2*)(&Ws[buf][row * 40 + gc4 * 4]) =                         \
                make_uint2(h2pack(pw[i].x, pw[i].y), h2pack(pw[i].z, pw[i].w)); \
        }                                                                     \
    }

    QKV_LOAD(0);
    QKV_STS(0);
    QKV_LOAD(1);
    __syncthreads();

#pragma unroll
    for (int ch = 0; ch < 8; ch++) {
        const int buf = ch & 1;
        const uint32 boff = buf * (64 * 40 * 2);

        uint32 aF[2][2][4];
#pragma unroll
        for (int mt = 0; mt < 2; mt++)
#pragma unroll
            for (int ks = 0; ks < 2; ks++)
                ldsm4(aF[mt][ks][0], aF[mt][ks][1], aF[mt][ks][2], aF[mt][ks][3],
                      aAddr[mt][ks] + boff);
        uint32 bF[4][2][2];
#pragma unroll
        for (int pr = 0; pr < 2; pr++)
#pragma unroll
            for (int ks = 0; ks < 2; ks++) {
                uint32 r0, r1, r2, r3;
                ldsm4(r0, r1, r2, r3, bAddr[pr][ks] + boff);
                bF[2 * pr][ks][0] = r0; bF[2 * pr][ks][1] = r1;
                bF[2 * pr + 1][ks][0] = r2; bF[2 * pr + 1][ks][1] = r3;
            }

        if (ch < 7) QKV_STS(buf ^ 1);
        if (ch < 6) QKV_LOAD(ch + 2);
        __syncthreads();

#pragma unroll
        for (int ks = 0; ks < 2; ks++)
#pragma unroll
            for (int mt = 0; mt < 2; mt++)
#pragma unroll
                for (int nt = 0; nt < 4; nt++)
                    mma_f16(C[mt][nt], aF[mt][ks], bF[nt][ks][0], bF[nt][ks][1]);
    }

    // ---- epilogue: rope + scatter into smem, then coalesced global copy ----
    const float QS = 0.17677669529663687f * 1.4426950408889634f;
    __half* ebufh = (__half*)ebuf;
#pragma unroll
    for (int mt = 0; mt < 2; mt++) {
        int row0 = m0 + wm * 32 + mt * 16 + quad;
#pragma unroll
        for (int nt = 0; nt < 4; nt++) {
            int col = n0 + wn * 32 + nt * 8 + 2 * cm;
            float b0 = bias[col], b1 = bias[col + 1];
            int hl = (col & 63) >> 5;
            int d = col & 31;
#pragma unroll
            for (int half_ = 0; half_ < 2; half_++) {
                int row = row0 + half_ * 8;
                float real = C[mt][nt][half_ * 2 + 0] + b0;
                float imag = C[mt][nt][half_ * 2 + 1] + b1;
                int lloc = row & 63;
                if (mode == 2) {
                    int kst2 = lloc >> 4, rk = lloc & 15;
                    int plane = rk >> 3, t4 = (rk & 7) >> 1, lh = rk & 1;
                    int nd = d >> 3, g0 = d & 7;
                    int baseloc = ((kst2 * 2 + (nd >> 1)) * 32) * 4 + (nd & 1) * 2 + plane;
                    int i0 = (baseloc + (g0 * 4 + t4) * 4) * 2 + lh;
                    int i1 = (baseloc + ((g0 + 1) * 4 + t4) * 4) * 2 + lh;
                    ebufh[hl * 2048 + i0] = __float2half(real);
                    ebufh[hl * 2048 + i1] = __float2half(imag);
                } else {
                    int l = row & 4095;
                    int p = d >> 1;
                    float cs = g_cos[l * NPAIR + p];
                    float sn = g_sin[l * NPAIR + p];
                    float out_r = real * cs - imag * sn;
                    float out_i = real * sn + imag * cs;
                    if (mode == 0) { out_r *= QS; out_i *= QS; }
                    uint32 packed = h2pack(out_r, out_i);
                    int ks = d >> 4, dc = d & 15;
                    if (mode == 0) {
                        int rg_local = lloc >> 4, r = lloc & 15;
                        int areg = (r >> 3) + ((dc >> 3) << 1);
                        int ln = (r & 7) * 4 + ((dc & 7) >> 1);
                        ebuf[hl * 1024 + ((rg_local * 2 + ks) * 4 + areg) * 32 + ln] = packed;
                    } else {
                        int ng = lloc >> 3;
                        int plane = dc >> 3;
                        int ln = (lloc & 7) * 4 + ((dc & 7) >> 1);
                        ebuf[hl * 1024 + (ng * 32 + ln) * 4 + ks * 2 + plane] = packed;
                    }
                }
            }
        }
    }
    __syncthreads();

    {
        int b = m0 >> 12;
        int h0 = n0 >> 5;
        uint32* garr = (mode == 0) ? g_qh2 : (mode == 1) ? g_kh2 : g_vh2;
        int blockbase = (mode == 0) ? (((m0 & 4095) >> 4) * 256)
                                    : (((m0 & 4095) >> 6) * 1024);
#pragma unroll
        for (int i = 0; i < 4; i++) {
            int slot = tid + 128 * i;
            int hl = slot >> 8, off = slot & 255;
            uint4 v = ((const uint4*)ebuf)[hl * 256 + off];
            size_t gb = (size_t)((b * 8 + h0 + hl)) * 65536 + blockbase;
            *(uint4*)(garr + gb + off * 4) = v;
        }
    }
}

// ---------------- output projection: A as direct frag LDG, W via smem -----
__global__ __launch_bounds__(128, 5)
void gemm_out(const float* __restrict__ W, const float* __restrict__ bias,
              float* __restrict__ out) {
    __shared__ __align__(16) __half Wh[2][64 * 40];
    __shared__ __align__(16) __half Wl[2][64 * 40];

    const int tid = threadIdx.x;
    const int w = tid >> 5, lane = tid & 31;
    const int quad = lane >> 2, cm = lane & 3;
    const int wm = w >> 1, wn = w & 1;
    const int m0 = blockIdx.y * 64;
    const int n0 = blockIdx.x * 64;

    float C[2][4][4];
#pragma unroll
    for (int mt = 0; mt < 2; mt++)
#pragma unroll
        for (int nt = 0; nt < 4; nt++)
#pragma unroll
            for (int j = 0; j < 4; j++) C[mt][nt][j] = 0.0f;

    const uint32 whb = (uint32)__cvta_generic_to_shared(&Wh[0][0]);
    const uint32 wlb = (uint32)__cvta_generic_to_shared(&Wl[0][0]);
    const int matid = lane >> 3, rowin = lane & 7;
    uint32 bOff[2][2];
#pragma unroll
    for (int pr = 0; pr < 2; pr++)
#pragma unroll
        for (int ks = 0; ks < 2; ks++) {
            int n = wn * 32 + (pr * 2 + (matid >> 1)) * 8 + rowin;
            int kc = ks * 16 + (matid & 1) * 8;
            bOff[pr][ks] = (n * 40 + kc) * 2;
        }

    // A rowgroup indices (global over m=8192)
    const int rg0 = (m0 + wm * 32) >> 4;         // mt=0
    const int rg1 = rg0 + 1;                     // mt=1

    float4 pw[4];
    const int grow = tid >> 3, gc4 = tid & 7;

#define OUTW_LOAD(ch)                                                         \
    {                                                                         \
        _Pragma("unroll")                                                     \
        for (int i = 0; i < 4; i++) {                                         \
            int row = grow + 16 * i;                                          \
            pw[i] = *(const float4*)(W + (size_t)(n0 + row) * 256 + (ch) * 32 + gc4 * 4); \
        }                                                                     \
    }
#define OUTW_STS(buf)                                                         \
    {                                                                         \
        _Pragma("unroll")                                                     \
        for (int i = 0; i < 4; i++) {                                         \
            int row = grow + 16 * i;                                          \
            uint2 hi, lo;                                                     \
            split4h(pw[i], hi, lo);                                           \
            *(uint2*)(&Wh[buf][row * 40 + gc4 * 4]) = hi;                     \
            *(uint2*)(&Wl[buf][row * 40 + gc4 * 4]) = lo;                     \
        }                                                                     \
    }

    OUTW_LOAD(0);
    OUTW_STS(0);
    OUTW_LOAD(1);
    __syncthreads();

#pragma unroll
    for (int ch = 0; ch < 8; ch++) {
        const int buf = ch & 1;
        const uint32 boff = buf * (64 * 40 * 2);

        // A fragments direct from global (hi & lo planes)
        uint4 aH[2][2], aL[2][2];
#pragma unroll
        for (int ks = 0; ks < 2; ks++) {
            int ksg = ch * 2 + ks;
            aH[0][ks] = g_aoh[(rg0 * 16 + ksg) * 32 + lane];
            aH[1][ks] = g_aoh[(rg1 * 16 + ksg) * 32 + lane];
            aL[0][ks] = g_aol[(rg0 * 16 + ksg) * 32 + lane];
            aL[1][ks] = g_aol[(rg1 * 16 + ksg) * 32 + lane];
        }

        uint32 bH[4][2][2], bL[4][2][2];
#pragma unroll
        for (int pr = 0; pr < 2; pr++)
#pragma unroll
            for (int ks = 0; ks < 2; ks++) {
                uint32 r0, r1, r2, r3;
                ldsm4(r0, r1, r2, r3, whb + bOff[pr][ks] + boff);
                bH[2 * pr][ks][0] = r0; bH[2 * pr][ks][1] = r1;
                bH[2 * pr + 1][ks][0] = r2; bH[2 * pr + 1][ks][1] = r3;
                ldsm4(r0, r1, r2, r3, wlb + bOff[pr][ks] + boff);
                bL[2 * pr][ks][0] = r0; bL[2 * pr][ks][1] = r1;
                bL[2 * pr + 1][ks][0] = r2; bL[2 * pr + 1][ks][1] = r3;
            }

        if (ch < 7) OUTW_STS(buf ^ 1);
        if (ch < 6) OUTW_LOAD(ch + 2);
        __syncthreads();

#pragma unroll
        for (int ks = 0; ks < 2; ks++)
#pragma unroll
            for (int mt = 0; mt < 2; mt++)
#pragma unroll
                for (int nt = 0; nt < 4; nt++) {
                    mma_f16(C[mt][nt], (const uint32*)&aH[mt][ks], bH[nt][ks][0], bH[nt][ks][1]);
                    mma_f16(C[mt][nt], (const uint32*)&aL[mt][ks], bH[nt][ks][0], bH[nt][ks][1]);
                    mma_f16(C[mt][nt], (const uint32*)&aH[mt][ks], bL[nt][ks][0], bL[nt][ks][1]);
                }
    }

#pragma unroll
    for (int mt = 0; mt < 2; mt++) {
        int row0 = m0 + wm * 32 + mt * 16 + quad;
#pragma unroll
        for (int nt = 0; nt < 4; nt++) {
            int col = n0 + wn * 32 + nt * 8 + 2 * cm;
            float b0 = bias[col], b1 = bias[col + 1];
#pragma unroll
            for (int half_ = 0; half_ < 2; half_++) {
                int row = row0 + half_ * 8;
                float real = C[mt][nt][half_ * 2 + 0] + b0;
                float imag = C[mt][nt][half_ * 2 + 1] + b1;
                *(float2*)(out + (size_t)row * 256 + col) = make_float2(real, imag);
            }
        }
    }
}

// ---------------- flash attention: QT=64 balanced, packed LDS.128 ---------
__global__ __launch_bounds__(128, 7)
void attn_mma() {
    __shared__ __align__(16) uint32 sK[2][1024];
    __shared__ __align__(16) uint32 sV[2][1024];

    const int tid = threadIdx.x;
    const int w = tid >> 5;
    const int lane = tid & 31;
    const int bh = blockIdx.y;
    const int q0 = blockIdx.x * QT;
    const uint32 ONES2 = 0x3C003C00u;

    const uint32* Q2 = g_qh2 + (size_t)bh * 65536;
    const uint32* K2 = g_kh2 + (size_t)bh * 65536;
    const uint32* V2 = g_vh2 + (size_t)bh * 65536;

    uint32 qf[2][4];
    {
        int rg = (q0 >> 4) + w;
#pragma unroll
        for (int ks = 0; ks < 2; ks++)
#pragma unroll
            for (int ar = 0; ar < 4; ar++)
                qf[ks][ar] = Q2[((rg * 2 + ks) * 4 + ar) * 32 + lane];
    }

    float O[4][4];
#pragma unroll
    for (int nd = 0; nd < 4; nd++)
#pragma unroll
        for (int j = 0; j < 4; j++) O[nd][j] = 0.0f;

    float Lac[4] = {0.f, 0.f, 0.f, 0.f};

    const uint32 sKb = (uint32)__cvta_generic_to_shared(&sK[0][0]);
    const uint32 sVb = (uint32)__cvta_generic_to_shared(&sV[0][0]);

    {
        const float4* Kg = (const float4*)K2;
        const float4* Vg = (const float4*)V2;
#pragma unroll
        for (int i = 0; i < 2; i++) {
            cp16(sKb + (tid + 128 * i) * 16, Kg + tid + 128 * i);
            cp16(sVb + (tid + 128 * i) * 16, Vg + tid + 128 * i);
        }
        asm volatile("cp.async.commit_group;");
    }

    for (int t = 0; t < LL / 64; t++) {
        const int buf = t & 1;
        if (t + 1 < LL / 64) {
            const float4* Kg = (const float4*)(K2 + (size_t)(t + 1) * 1024);
            const float4* Vg = (const float4*)(V2 + (size_t)(t + 1) * 1024);
            uint32 dK = sKb + (buf ^ 1) * 4096;
            uint32 dV = sVb + (buf ^ 1) * 4096;
#pragma unroll
            for (int i = 0; i < 2; i++) {
                cp16(dK + (tid + 128 * i) * 16, Kg + tid + 128 * i);
                cp16(dV + (tid + 128 * i) * 16, Vg + tid + 128 * i);
            }
            asm volatile("cp.async.commit_group;");
            asm volatile("cp.async.wait_group 1;");
        } else {
            asm volatile("cp.async.wait_group 0;");
        }
        __syncthreads();

        const uint4* Kt = (const uint4*)sK[buf];
        const uint4* Vt = (const uint4*)sV[buf];

        uint32 aP[4];

#pragma unroll
        for (int n = 0; n < 8; n++) {
            uint4 kb = Kt[n * 32 + lane];
            float S[4] = {0.f, 0.f, 0.f, 0.f};
            mma_f16(S, qf[0], kb.x, kb.y);
            mma_f16(S, qf[1], kb.z, kb.w);

            const int off = (n & 1) * 2;
            aP[off + 0] = ex2h2(h2pack(S[0], S[1]));
            aP[off + 1] = ex2h2(h2pack(S[2], S[3]));

            if (n & 1) {
                const int kst2 = n >> 1;
                mma_f16(Lac, aP, ONES2, ONES2);
                uint4 v01 = Vt[(kst2 * 2 + 0) * 32 + lane];
                uint4 v23 = Vt[(kst2 * 2 + 1) * 32 + lane];
                mma_f16(O[0], aP, v01.x, v01.y);
                mma_f16(O[1], aP, v01.z, v01.w);
                mma_f16(O[2], aP, v23.x, v23.y);
                mma_f16(O[3], aP, v23.z, v23.w);
            }
        }
        __syncthreads();
    }

    // ---- epilogue: normalize + emit hi/lo fp16 A-fragments for gemm_out ---
    float i0 = 1.0f / Lac[0];
    float i1 = 1.0f / Lac[2];
    int b = bh >> 3, h = bh & 7;
    int rg = b * 256 + ((q0 + w * 16) >> 4);
#pragma unroll
    for (int ks = 0; ks < 2; ks++) {
        uint32 h0, h1, h2_, h3, l0, l1, l2, l3;
        pack_hilo(O[2 * ks][0] * i0, O[2 * ks][1] * i0, h0, l0);
        pack_hilo(O[2 * ks][2] * i1, O[2 * ks][3] * i1, h1, l1);
        pack_hilo(O[2 * ks + 1][0] * i0, O[2 * ks + 1][1] * i0, h2_, l2);
        pack_hilo(O[2 * ks + 1][2] * i1, O[2 * ks + 1][3] * i1, h3, l3);
        int ksg = h * 2 + ks;
        g_aoh[(rg * 16 + ksg) * 32 + lane] = make_uint4(h0, h1, h2_, h3);
        g_aol[(rg * 16 + ksg) * 32 + lane] = make_uint4(l0, l1, l2, l3);
    }
}

// ---------------- launcher ----------------
extern "C" void kernel_launch(void* const* d_in, const int* in_sizes, int n_in,
                              void* d_out, int out_size) {
    const float* q  = (const float*)d_in[0];
    const float* k  = (const float*)d_in[1];
    const float* v  = (const float*)d_in[2];
    const float* Wq = (const float*)d_in[3];
    const float* bq = (const float*)d_in[4];
    const float* Wk = (const float*)d_in[5];
    const float* bk = (const float*)d_in[6];
    const float* Wv = (const float*)d_in[7];
    const float* bv = (const float*)d_in[8];
    const float* Wo = (const float*)d_in[9];
    const float* bo = (const float*)d_in[10];
    float* out = (float*)d_out;

    rope_table_kernel<<<(LL * NPAIR + 255) / 256, 256>>>();

    dim3 g3(EE / 64, (BB * LL) / 64, 3);  // (4, 128, 3) — fused Q/K/V
    gemm_qkv<<<g3, 128>>>(q, k, v, Wq, Wk, Wv, bq, bk, bv);

    attn_mma<<<dim3(LL / QT, BB * HH), 128>>>();   // (64, 16)

    dim3 gg(EE / 64, (BB * LL) / 64);  // (4, 128)
    gemm_out<<<gg, 128>>>(Wo, bo, out);
}